// round 6
// baseline (speedup 1.0000x reference)
#include <cuda_runtime.h>
#include <cuda_fp16.h>
#include <mma.h>
#include <math.h>

using namespace nvcuda;

// Problem constants
constexpr int B_  = 4;
constexpr int S_  = 2048;
constexpr int E_  = 1152;
constexpr int H_  = 12;
constexpr int D_  = 96;
constexpr int HD_ = H_ * D_;     // 1152
constexpr int QKV_ = 3 * HD_;    // 3456
constexpr int M_  = B_ * S_;     // 8192
constexpr int BH_ = B_ * H_;     // 48

// ---------------------------------------------------------------------------
// Scratch (device globals: the allocation-free path)
// ---------------------------------------------------------------------------
__device__ __half g_logits_h[(size_t)M_ * E_];
__device__ __half g_Wqkv_h[(size_t)E_ * QKV_];
__device__ __half g_Wo_h[(size_t)HD_ * E_];
__device__ float  g_qkvf[(size_t)M_ * QKV_];
__device__ __half g_qh[(size_t)M_ * HD_];
__device__ __half g_kh[(size_t)M_ * HD_];
__device__ __half g_vh[(size_t)M_ * HD_];
__device__ __half g_ctxh[(size_t)M_ * HD_];

// ---------------------------------------------------------------------------
// cp.async helpers
// ---------------------------------------------------------------------------
__device__ __forceinline__ unsigned smem_u32(const void* p) {
    return (unsigned)__cvta_generic_to_shared(p);
}
__device__ __forceinline__ void cp16(unsigned s, const void* g) {
    asm volatile("cp.async.cg.shared.global [%0], [%1], 16;\n" :: "r"(s), "l"(g));
}
__device__ __forceinline__ void cp_commit() {
    asm volatile("cp.async.commit_group;\n");
}
__device__ __forceinline__ void cp_wait0() {
    asm volatile("cp.async.wait_group 0;\n");
}

// ---------------------------------------------------------------------------
// Elementwise converts
// ---------------------------------------------------------------------------
__global__ void cvt_inputs(const float* __restrict__ logits,
                           const float* __restrict__ Wq,
                           const float* __restrict__ Wk,
                           const float* __restrict__ Wv,
                           const float* __restrict__ Wo) {
    int i = blockIdx.x * blockDim.x + threadIdx.x;
    if (i < M_ * E_) g_logits_h[i] = __float2half(logits[i]);
    if (i < E_ * HD_) {
        int r = i / HD_, c = i % HD_;
        size_t o = (size_t)r * QKV_ + c;
        g_Wqkv_h[o]           = __float2half(Wq[i]);
        g_Wqkv_h[o + HD_]     = __float2half(Wk[i]);
        g_Wqkv_h[o + 2 * HD_] = __float2half(Wv[i]);
        g_Wo_h[i] = __float2half(Wo[i]);
    }
}

// ---------------------------------------------------------------------------
// Big GEMM: C[M,N] = A[M,1152] @ B[1152,N] (+ bias), fp16 in, fp32 out.
// Block tile 128x128, BK=32, double-buffered cp.async, 8 warps (4x2),
// each warp a 32x64 C tile (2x4 accum fragments).
// ---------------------------------------------------------------------------
template<int N>
__global__ __launch_bounds__(256, 2) void gemm_big(const __half* __restrict__ A,
                                                   const __half* __restrict__ Bw,
                                                   float* __restrict__ C,
                                                   const float* __restrict__ bias) {
    __shared__ __half As[2][128][40];
    __shared__ __half Bs[2][32][136];
    const int bm = blockIdx.y * 128;
    const int bn = blockIdx.x * 128;
    const int tid = threadIdx.x;
    const int warp = tid >> 5, wr = warp >> 1, wc = warp & 1;
    const int lane = tid & 31;

    const int ar0 = tid >> 2, ac = (tid & 3) * 8;
    const int br0 = tid >> 4, bc = (tid & 15) * 8;

    wmma::fragment<wmma::accumulator, 16, 16, 16, float> acc[2][4];
#pragma unroll
    for (int i = 0; i < 2; ++i)
#pragma unroll
        for (int j = 0; j < 4; ++j) wmma::fill_fragment(acc[i][j], 0.0f);

    {
        cp16(smem_u32(&As[0][ar0][ac]),      &A[(size_t)(bm + ar0) * 1152 + ac]);
        cp16(smem_u32(&As[0][ar0 + 64][ac]), &A[(size_t)(bm + ar0 + 64) * 1152 + ac]);
        cp16(smem_u32(&Bs[0][br0][bc]),      &Bw[(size_t)br0 * N + bn + bc]);
        cp16(smem_u32(&Bs[0][br0 + 16][bc]), &Bw[(size_t)(br0 + 16) * N + bn + bc]);
        cp_commit();
    }

    int buf = 0;
    constexpr int NIT = 1152 / 32;
    for (int it = 0; it < NIT; ++it) {
        cp_wait0();
        __syncthreads();
        if (it + 1 < NIT) {
            const int k0 = (it + 1) * 32;
            const int nb = buf ^ 1;
            cp16(smem_u32(&As[nb][ar0][ac]),      &A[(size_t)(bm + ar0) * 1152 + k0 + ac]);
            cp16(smem_u32(&As[nb][ar0 + 64][ac]), &A[(size_t)(bm + ar0 + 64) * 1152 + k0 + ac]);
            cp16(smem_u32(&Bs[nb][br0][bc]),      &Bw[(size_t)(k0 + br0) * N + bn + bc]);
            cp16(smem_u32(&Bs[nb][br0 + 16][bc]), &Bw[(size_t)(k0 + br0 + 16) * N + bn + bc]);
            cp_commit();
        }
#pragma unroll
        for (int kk = 0; kk < 32; kk += 16) {
            wmma::fragment<wmma::matrix_a, 16, 16, 16, __half, wmma::row_major> a0, a1;
            wmma::load_matrix_sync(a0, &As[buf][wr * 32][kk], 40);
            wmma::load_matrix_sync(a1, &As[buf][wr * 32 + 16][kk], 40);
#pragma unroll
            for (int j = 0; j < 4; ++j) {
                wmma::fragment<wmma::matrix_b, 16, 16, 16, __half, wmma::row_major> bf;
                wmma::load_matrix_sync(bf, &Bs[buf][kk][wc * 64 + j * 16], 136);
                wmma::mma_sync(acc[0][j], a0, bf, acc[0][j]);
                wmma::mma_sync(acc[1][j], a1, bf, acc[1][j]);
            }
        }
        buf ^= 1;
    }

#pragma unroll
    for (int i = 0; i < 2; ++i)
#pragma unroll
        for (int j = 0; j < 4; ++j) {
            if (bias) {
#pragma unroll
                for (int e = 0; e < 8; ++e) {
                    int c = (lane & 3) * 2 + (e & 1) + ((e >> 2) & 1) * 8;
                    acc[i][j].x[e] += bias[bn + wc * 64 + j * 16 + c];
                }
            }
            wmma::store_matrix_sync(
                &C[(size_t)(bm + wr * 32 + i * 16) * N + bn + wc * 64 + j * 16],
                acc[i][j], N, wmma::mem_row_major);
        }
}

// ---------------------------------------------------------------------------
// RoPE + bias + fp16 pack for q,k; bias + fp16 pack for v. Reads fused qkv.
// ---------------------------------------------------------------------------
__global__ void rope_pack(const float* __restrict__ bq,
                          const float* __restrict__ bk,
                          const float* __restrict__ bv) {
    const int NP = B_ * S_ * H_ * (D_ / 2);
    int gid = blockIdx.x * blockDim.x + threadIdx.x;
    if (gid >= NP) return;
    int j = gid % (D_ / 2);
    int t = gid / (D_ / 2);
    int h = t % H_; t /= H_;
    int s = t % S_;
    int b = t / S_;

    const size_t row = (size_t)(b * S_ + s);
    const int col = h * D_ + 2 * j;
    const size_t src = row * QKV_ + col;
    const size_t dst = row * HD_ + col;

    double theta = exp(-(2.0 * (double)j / (double)D_) * log(10000.0));
    float angf = (float)s * (float)theta;
    double sn, cs;
    sincos((double)angf, &sn, &cs);
    float c = (float)cs, snf = (float)sn;

    float q0 = g_qkvf[src]     + bq[col];
    float q1 = g_qkvf[src + 1] + bq[col + 1];
    g_qh[dst]     = __float2half(q0 * c - q1 * snf);
    g_qh[dst + 1] = __float2half(q1 * c + q0 * snf);

    float k0 = g_qkvf[src + HD_]     + bk[col];
    float k1 = g_qkvf[src + HD_ + 1] + bk[col + 1];
    g_kh[dst]     = __float2half(k0 * c - k1 * snf);
    g_kh[dst + 1] = __float2half(k1 * c + k0 * snf);

    g_vh[dst]     = __float2half(g_qkvf[src + 2 * HD_]     + bv[col]);
    g_vh[dst + 1] = __float2half(g_qkvf[src + 2 * HD_ + 1] + bv[col + 1]);
}

// ---------------------------------------------------------------------------
// Fused flash attention (causal, online softmax).
// Per CTA: 128 q-rows of one (b,h). k-tiles of 64, K=D=96.
// 8 warps (4x2): S tile warp = 32x32 (2x2 frags), O tile warp = 32x48 (2x3).
// O accumulated in fragments, rescaled per tile with corr = exp(m_old-m_new)
// using the Ampere+ accumulator row map (rows lane/4 and lane/4+8).
// grid = (16, 48) with q-tile index reversed (heavy blocks first).
// ---------------------------------------------------------------------------
struct FlashSmem {
    __half Qs[128][104];
    __half Ks[64][104];
    __half Vs[64][104];
    float  Ss[128][68];
    __half Ps[128][72];
    float  m_s[128];
    float  l_s[128];
    float  corr_s[128];
    float  stage[8][16][24];
};

__global__ __launch_bounds__(256) void flash_attn() {
    extern __shared__ char smraw[];
    FlashSmem& sm = *reinterpret_cast<FlashSmem*>(smraw);
    const int qi = gridDim.x - 1 - blockIdx.x;      // heavy tiles first
    const int qb = qi * 128;
    const int bh = blockIdx.y, b = bh / H_, h = bh % H_;
    const __half* Q = g_qh + (size_t)b * S_ * HD_ + h * D_;
    const __half* K = g_kh + (size_t)b * S_ * HD_ + h * D_;
    const __half* V = g_vh + (size_t)b * S_ * HD_ + h * D_;
    const int tid = threadIdx.x, lane = tid & 31;
    const int warp = tid >> 5, wr = warp >> 1, wc = warp & 1;
    const float SCALE = 0.10206207261596577f;       // 1/sqrt(96)

    // Load Q tile (128 x 96)
    for (int i = tid; i < 1536; i += 256) {
        int r = i / 12, c = (i % 12) * 8;
        *reinterpret_cast<uint4*>(&sm.Qs[r][c]) =
            *reinterpret_cast<const uint4*>(&Q[(size_t)(qb + r) * HD_ + c]);
    }
    if (tid < 128) { sm.m_s[tid] = -1e30f; sm.l_s[tid] = 0.0f; }

    wmma::fragment<wmma::accumulator, 16, 16, 16, float> oacc[2][3];
#pragma unroll
    for (int i = 0; i < 2; ++i)
#pragma unroll
        for (int j = 0; j < 3; ++j) wmma::fill_fragment(oacc[i][j], 0.0f);

    const int ktiles = (qb + 128) / 64;
    for (int t = 0; t < ktiles; ++t) {
        const int k0 = t * 64;
        __syncthreads();                            // prev PV done; state visible
        for (int i = tid; i < 768; i += 256) {      // K,V tiles (64 x 96 each)
            int r = i / 12, c = (i % 12) * 8;
            *reinterpret_cast<uint4*>(&sm.Ks[r][c]) =
                *reinterpret_cast<const uint4*>(&K[(size_t)(k0 + r) * HD_ + c]);
            *reinterpret_cast<uint4*>(&sm.Vs[r][c]) =
                *reinterpret_cast<const uint4*>(&V[(size_t)(k0 + r) * HD_ + c]);
        }
        __syncthreads();

        // S = scale * Q @ K^T  -> Ss (fp32 smem)
        wmma::fragment<wmma::accumulator, 16, 16, 16, float> sacc[2][2];
#pragma unroll
        for (int i = 0; i < 2; ++i)
#pragma unroll
            for (int j = 0; j < 2; ++j) wmma::fill_fragment(sacc[i][j], 0.0f);
#pragma unroll
        for (int kk = 0; kk < 96; kk += 16) {
            wmma::fragment<wmma::matrix_a, 16, 16, 16, __half, wmma::row_major> a0, a1;
            wmma::load_matrix_sync(a0, &sm.Qs[wr * 32][kk], 104);
            wmma::load_matrix_sync(a1, &sm.Qs[wr * 32 + 16][kk], 104);
#pragma unroll
            for (int j = 0; j < 2; ++j) {
                wmma::fragment<wmma::matrix_b, 16, 16, 16, __half, wmma::col_major> bf;
                wmma::load_matrix_sync(bf, &sm.Ks[wc * 32 + j * 16][kk], 104);
                wmma::mma_sync(sacc[0][j], a0, bf, sacc[0][j]);
                wmma::mma_sync(sacc[1][j], a1, bf, sacc[1][j]);
            }
        }
#pragma unroll
        for (int i = 0; i < 2; ++i)
#pragma unroll
            for (int j = 0; j < 2; ++j) {
#pragma unroll
                for (int e = 0; e < 8; ++e) sacc[i][j].x[e] *= SCALE;
                wmma::store_matrix_sync(&sm.Ss[wr * 32 + i * 16][wc * 32 + j * 16],
                                        sacc[i][j], 68, wmma::mem_row_major);
            }
        __syncthreads();

        // Online softmax: 2 threads per row, 32 cols each.
        {
            const int row = tid >> 1, cb = (tid & 1) * 32;
            const bool full = (k0 + 64 <= qb);      // no masking in this tile
            const int lim = qb + row - k0;          // allowed: cc <= lim
            float mx = -1e30f;
#pragma unroll
            for (int c = 0; c < 32; ++c) {
                int cc = cb + c;
                if (full || cc <= lim) mx = fmaxf(mx, sm.Ss[row][cc]);
            }
            mx = fmaxf(mx, __shfl_xor_sync(0xffffffffu, mx, 1));
            float mold = sm.m_s[row];
            float mnew = fmaxf(mold, mx);
            float corr = __expf(mold - mnew);
            float ssum = 0.0f;
#pragma unroll
            for (int c = 0; c < 32; ++c) {
                int cc = cb + c;
                float p = 0.0f;
                if (full || cc <= lim) { p = __expf(sm.Ss[row][cc] - mnew); ssum += p; }
                sm.Ps[row][cc] = __float2half(p);
            }
            ssum += __shfl_xor_sync(0xffffffffu, ssum, 1);
            if ((tid & 1) == 0) {
                sm.m_s[row] = mnew;
                sm.l_s[row] = sm.l_s[row] * corr + ssum;
                sm.corr_s[row] = corr;
            }
        }
        __syncthreads();

        // Rescale O by corr (accumulator rows: lane/4 and lane/4 + 8)
#pragma unroll
        for (int i = 0; i < 2; ++i) {
            int r0 = wr * 32 + i * 16 + (lane >> 2);
            float c0 = sm.corr_s[r0], c1 = sm.corr_s[r0 + 8];
#pragma unroll
            for (int j = 0; j < 3; ++j)
#pragma unroll
                for (int e = 0; e < 8; ++e)
                    oacc[i][j].x[e] *= ((e >> 1) & 1) ? c1 : c0;
        }
        // O += P @ V
#pragma unroll
        for (int kk = 0; kk < 64; kk += 16) {
            wmma::fragment<wmma::matrix_a, 16, 16, 16, __half, wmma::row_major> a0, a1;
            wmma::load_matrix_sync(a0, &sm.Ps[wr * 32][kk], 72);
            wmma::load_matrix_sync(a1, &sm.Ps[wr * 32 + 16][kk], 72);
#pragma unroll
            for (int j = 0; j < 3; ++j) {
                wmma::fragment<wmma::matrix_b, 16, 16, 16, __half, wmma::row_major> bf;
                wmma::load_matrix_sync(bf, &sm.Vs[kk][wc * 48 + j * 16], 104);
                wmma::mma_sync(oacc[0][j], a0, bf, oacc[0][j]);
                wmma::mma_sync(oacc[1][j], a1, bf, oacc[1][j]);
            }
        }
    }
    __syncthreads();

    // Epilogue: stage fp32, normalize by 1/l (plain row index), write fp16.
#pragma unroll
    for (int i = 0; i < 2; ++i)
#pragma unroll
        for (int j = 0; j < 3; ++j) {
            wmma::store_matrix_sync(&sm.stage[warp][0][0], oacc[i][j], 24,
                                    wmma::mem_row_major);
            __syncwarp();
#pragma unroll
            for (int u = 0; u < 8; ++u) {
                int idx = lane * 8 + u;
                int r = idx >> 4, c = idx & 15;
                int rowl = wr * 32 + i * 16 + r;
                float val = sm.stage[warp][r][c] / sm.l_s[rowl];
                size_t o = (size_t)(b * S_ + qb + rowl) * HD_ +
                           h * D_ + wc * 48 + j * 16 + c;
                g_ctxh[o] = __float2half(val);
            }
            __syncwarp();
        }
}

// ---------------------------------------------------------------------------
// Launch
// ---------------------------------------------------------------------------
extern "C" void kernel_launch(void* const* d_in, const int* in_sizes, int n_in,
                              void* d_out, int out_size) {
    (void)in_sizes; (void)n_in; (void)out_size;
    const float* logits = (const float*)d_in[0];
    const float* Wq = (const float*)d_in[1];
    const float* bq = (const float*)d_in[2];
    const float* Wk = (const float*)d_in[3];
    const float* bk = (const float*)d_in[4];
    const float* Wv = (const float*)d_in[5];
    const float* bv = (const float*)d_in[6];
    const float* Wo = (const float*)d_in[7];
    const float* bo = (const float*)d_in[8];
    float* out = (float*)d_out;

    cudaFuncSetAttribute(flash_attn, cudaFuncAttributeMaxDynamicSharedMemorySize,
                         (int)sizeof(FlashSmem));

    cvt_inputs<<<(M_ * E_ + 255) / 256, 256>>>(logits, Wq, Wk, Wv, Wo);

    {   // fused QKV projection: [8192,1152] @ [1152,3456]
        __half* A; cudaGetSymbolAddress((void**)&A, g_logits_h);
        __half* W; cudaGetSymbolAddress((void**)&W, g_Wqkv_h);
        float*  C; cudaGetSymbolAddress((void**)&C, g_qkvf);
        gemm_big<QKV_><<<dim3(QKV_ / 128, M_ / 128), 256>>>(A, W, C, nullptr);
    }

    rope_pack<<<(B_ * S_ * H_ * (D_ / 2) + 255) / 256, 256>>>(bq, bk, bv);

    flash_attn<<<dim3(S_ / 128, BH_), 256, sizeof(FlashSmem)>>>();

    {   // output projection + bias: [8192,1152] @ [1152,1152] -> out
        __half* A; cudaGetSymbolAddress((void**)&A, g_ctxh);
        __half* W; cudaGetSymbolAddress((void**)&W, g_Wo_h);
        gemm_big<E_><<<dim3(E_ / 128, M_ / 128), 256>>>(A, W, out, bo);
    }
}

// round 7
// speedup vs baseline: 1.3112x; 1.3112x over previous
#include <cuda_runtime.h>
#include <cuda_fp16.h>
#include <mma.h>
#include <math.h>

using namespace nvcuda;

// Problem constants
constexpr int B_  = 4;
constexpr int S_  = 2048;
constexpr int E_  = 1152;
constexpr int H_  = 12;
constexpr int D_  = 96;
constexpr int HD_ = H_ * D_;     // 1152
constexpr int QKV_ = 3 * HD_;    // 3456
constexpr int M_  = B_ * S_;     // 8192
constexpr int BH_ = B_ * H_;     // 48

// ---------------------------------------------------------------------------
// Scratch (device globals: the allocation-free path)
// ---------------------------------------------------------------------------
__device__ __half g_logits_h[(size_t)M_ * E_];
__device__ __half g_Wqkv_h[(size_t)E_ * QKV_];
__device__ __half g_Wo_h[(size_t)HD_ * E_];
__device__ float  g_qkvf[(size_t)M_ * QKV_];
__device__ __half g_qh[(size_t)M_ * HD_];
__device__ __half g_kh[(size_t)M_ * HD_];
__device__ __half g_vh[(size_t)M_ * HD_];
__device__ __half g_ctxh[(size_t)M_ * HD_];

// ---------------------------------------------------------------------------
// cp.async helpers
// ---------------------------------------------------------------------------
__device__ __forceinline__ unsigned smem_u32(const void* p) {
    return (unsigned)__cvta_generic_to_shared(p);
}
__device__ __forceinline__ void cp16(unsigned s, const void* g) {
    asm volatile("cp.async.cg.shared.global [%0], [%1], 16;\n" :: "r"(s), "l"(g));
}
__device__ __forceinline__ void cp_commit() {
    asm volatile("cp.async.commit_group;\n");
}
__device__ __forceinline__ void cp_wait0() {
    asm volatile("cp.async.wait_group 0;\n");
}

// ---------------------------------------------------------------------------
// Elementwise converts
// ---------------------------------------------------------------------------
__global__ void cvt_inputs(const float* __restrict__ logits,
                           const float* __restrict__ Wq,
                           const float* __restrict__ Wk,
                           const float* __restrict__ Wv,
                           const float* __restrict__ Wo) {
    int i = blockIdx.x * blockDim.x + threadIdx.x;
    if (i < M_ * E_) g_logits_h[i] = __float2half(logits[i]);
    if (i < E_ * HD_) {
        int r = i / HD_, c = i % HD_;
        size_t o = (size_t)r * QKV_ + c;
        g_Wqkv_h[o]           = __float2half(Wq[i]);
        g_Wqkv_h[o + HD_]     = __float2half(Wk[i]);
        g_Wqkv_h[o + 2 * HD_] = __float2half(Wv[i]);
        g_Wo_h[i] = __float2half(Wo[i]);
    }
}

// ---------------------------------------------------------------------------
// Big GEMM: C[M,N] = A[M,1152] @ B[1152,N] (+ bias), fp16 in, fp32 out.
// Block tile 128x128, BK=32, double-buffered cp.async, 8 warps (4x2).
// ---------------------------------------------------------------------------
template<int N>
__global__ __launch_bounds__(256, 2) void gemm_big(const __half* __restrict__ A,
                                                   const __half* __restrict__ Bw,
                                                   float* __restrict__ C,
                                                   const float* __restrict__ bias) {
    __shared__ __half As[2][128][40];
    __shared__ __half Bs[2][32][136];
    const int bm = blockIdx.y * 128;
    const int bn = blockIdx.x * 128;
    const int tid = threadIdx.x;
    const int warp = tid >> 5, wr = warp >> 1, wc = warp & 1;
    const int lane = tid & 31;

    const int ar0 = tid >> 2, ac = (tid & 3) * 8;
    const int br0 = tid >> 4, bc = (tid & 15) * 8;

    wmma::fragment<wmma::accumulator, 16, 16, 16, float> acc[2][4];
#pragma unroll
    for (int i = 0; i < 2; ++i)
#pragma unroll
        for (int j = 0; j < 4; ++j) wmma::fill_fragment(acc[i][j], 0.0f);

    {
        cp16(smem_u32(&As[0][ar0][ac]),      &A[(size_t)(bm + ar0) * 1152 + ac]);
        cp16(smem_u32(&As[0][ar0 + 64][ac]), &A[(size_t)(bm + ar0 + 64) * 1152 + ac]);
        cp16(smem_u32(&Bs[0][br0][bc]),      &Bw[(size_t)br0 * N + bn + bc]);
        cp16(smem_u32(&Bs[0][br0 + 16][bc]), &Bw[(size_t)(br0 + 16) * N + bn + bc]);
        cp_commit();
    }

    int buf = 0;
    constexpr int NIT = 1152 / 32;
    for (int it = 0; it < NIT; ++it) {
        cp_wait0();
        __syncthreads();
        if (it + 1 < NIT) {
            const int k0 = (it + 1) * 32;
            const int nb = buf ^ 1;
            cp16(smem_u32(&As[nb][ar0][ac]),      &A[(size_t)(bm + ar0) * 1152 + k0 + ac]);
            cp16(smem_u32(&As[nb][ar0 + 64][ac]), &A[(size_t)(bm + ar0 + 64) * 1152 + k0 + ac]);
            cp16(smem_u32(&Bs[nb][br0][bc]),      &Bw[(size_t)(k0 + br0) * N + bn + bc]);
            cp16(smem_u32(&Bs[nb][br0 + 16][bc]), &Bw[(size_t)(k0 + br0 + 16) * N + bn + bc]);
            cp_commit();
        }
#pragma unroll
        for (int kk = 0; kk < 32; kk += 16) {
            wmma::fragment<wmma::matrix_a, 16, 16, 16, __half, wmma::row_major> a0, a1;
            wmma::load_matrix_sync(a0, &As[buf][wr * 32][kk], 40);
            wmma::load_matrix_sync(a1, &As[buf][wr * 32 + 16][kk], 40);
#pragma unroll
            for (int j = 0; j < 4; ++j) {
                wmma::fragment<wmma::matrix_b, 16, 16, 16, __half, wmma::row_major> bf;
                wmma::load_matrix_sync(bf, &Bs[buf][kk][wc * 64 + j * 16], 136);
                wmma::mma_sync(acc[0][j], a0, bf, acc[0][j]);
                wmma::mma_sync(acc[1][j], a1, bf, acc[1][j]);
            }
        }
        buf ^= 1;
    }

#pragma unroll
    for (int i = 0; i < 2; ++i)
#pragma unroll
        for (int j = 0; j < 4; ++j) {
            if (bias) {
#pragma unroll
                for (int e = 0; e < 8; ++e) {
                    int c = (lane & 3) * 2 + (e & 1) + ((e >> 2) & 1) * 8;
                    acc[i][j].x[e] += bias[bn + wc * 64 + j * 16 + c];
                }
            }
            wmma::store_matrix_sync(
                &C[(size_t)(bm + wr * 32 + i * 16) * N + bn + wc * 64 + j * 16],
                acc[i][j], N, wmma::mem_row_major);
        }
}

// ---------------------------------------------------------------------------
// RoPE + bias + fp16 pack for q,k; bias + fp16 pack for v. Reads fused qkv.
// ---------------------------------------------------------------------------
__global__ void rope_pack(const float* __restrict__ bq,
                          const float* __restrict__ bk,
                          const float* __restrict__ bv) {
    const int NP = B_ * S_ * H_ * (D_ / 2);
    int gid = blockIdx.x * blockDim.x + threadIdx.x;
    if (gid >= NP) return;
    int j = gid % (D_ / 2);
    int t = gid / (D_ / 2);
    int h = t % H_; t /= H_;
    int s = t % S_;
    int b = t / S_;

    const size_t row = (size_t)(b * S_ + s);
    const int col = h * D_ + 2 * j;
    const size_t src = row * QKV_ + col;
    const size_t dst = row * HD_ + col;

    double theta = exp(-(2.0 * (double)j / (double)D_) * log(10000.0));
    float angf = (float)s * (float)theta;
    double sn, cs;
    sincos((double)angf, &sn, &cs);
    float c = (float)cs, snf = (float)sn;

    float q0 = g_qkvf[src]     + bq[col];
    float q1 = g_qkvf[src + 1] + bq[col + 1];
    g_qh[dst]     = __float2half(q0 * c - q1 * snf);
    g_qh[dst + 1] = __float2half(q1 * c + q0 * snf);

    float k0 = g_qkvf[src + HD_]     + bk[col];
    float k1 = g_qkvf[src + HD_ + 1] + bk[col + 1];
    g_kh[dst]     = __float2half(k0 * c - k1 * snf);
    g_kh[dst + 1] = __float2half(k1 * c + k0 * snf);

    g_vh[dst]     = __float2half(g_qkvf[src + 2 * HD_]     + bv[col]);
    g_vh[dst + 1] = __float2half(g_qkvf[src + 2 * HD_ + 1] + bv[col + 1]);
}

// ---------------------------------------------------------------------------
// Fused flash attention v2 (causal, online softmax, warp-local rows).
// CTA: 128 q-rows of one (b,h); 8 warps, warp w owns rows w*16..w*16+15.
// Per warp: S = 16x64 (4 frags), O = 16x96 (6 frags). Softmax fully in
// registers (quad shfl over accumulator layout: row = lane/4 + 8*((e>>1)&1),
// col = (lane&3)*2 + (e&1) + 8*((e>>2)&1)). m/l state in registers.
// K/V double-buffered via cp.async; ONE __syncthreads per k-tile.
// grid = (16, 48), q-tile reversed (heavy first); 2 CTAs/SM.
// ---------------------------------------------------------------------------
struct FlashSmem {
    __half Qs[128][104];
    __half Ks[2][64][104];
    __half Vs[2][64][104];
    __half Ps[128][72];
    float  l_s[128];
};

__global__ __launch_bounds__(256, 2) void flash_attn() {
    extern __shared__ char smraw[];
    FlashSmem& sm = *reinterpret_cast<FlashSmem*>(smraw);
    const int qi = gridDim.x - 1 - blockIdx.x;      // heavy tiles first
    const int qb = qi * 128;
    const int bh = blockIdx.y, b = bh / H_, h = bh % H_;
    const __half* Q = g_qh + (size_t)b * S_ * HD_ + h * D_;
    const __half* K = g_kh + (size_t)b * S_ * HD_ + h * D_;
    const __half* V = g_vh + (size_t)b * S_ * HD_ + h * D_;
    const int tid = threadIdx.x, lane = tid & 31, warp = tid >> 5;
    const float SCALE = 0.10206207261596577f;       // 1/sqrt(96)

    // Prologue: Q tile (128x96) + K/V tile 0 via cp.async
#pragma unroll
    for (int u = 0; u < 6; ++u) {
        int i = tid + 256 * u;                      // 0..1535
        int r = i / 12, c = (i % 12) * 8;
        cp16(smem_u32(&sm.Qs[r][c]), &Q[(size_t)(qb + r) * HD_ + c]);
    }
#pragma unroll
    for (int u = 0; u < 3; ++u) {
        int i = tid + 256 * u;                      // 0..767
        int r = i / 12, c = (i % 12) * 8;
        cp16(smem_u32(&sm.Ks[0][r][c]), &K[(size_t)r * HD_ + c]);
        cp16(smem_u32(&sm.Vs[0][r][c]), &V[(size_t)r * HD_ + c]);
    }
    cp_commit();

    float m0 = -1e30f, m1 = -1e30f, l0 = 0.0f, l1 = 0.0f;
    wmma::fragment<wmma::accumulator, 16, 16, 16, float> oacc[6];
#pragma unroll
    for (int j = 0; j < 6; ++j) wmma::fill_fragment(oacc[j], 0.0f);

    const int ktiles = (qb + 128) / 64;
    int buf = 0;
    for (int t = 0; t < ktiles; ++t) {
        const int k0 = t * 64;
        cp_wait0();
        __syncthreads();                            // K/V[buf] ready; prev tile done
        if (t + 1 < ktiles) {
            const int kn = k0 + 64, nb = buf ^ 1;
#pragma unroll
            for (int u = 0; u < 3; ++u) {
                int i = tid + 256 * u;
                int r = i / 12, c = (i % 12) * 8;
                cp16(smem_u32(&sm.Ks[nb][r][c]), &K[(size_t)(kn + r) * HD_ + c]);
                cp16(smem_u32(&sm.Vs[nb][r][c]), &V[(size_t)(kn + r) * HD_ + c]);
            }
            cp_commit();
        }

        // S = Q @ K^T : warp rows warp*16, cols 0..64
        wmma::fragment<wmma::accumulator, 16, 16, 16, float> sacc[4];
#pragma unroll
        for (int j = 0; j < 4; ++j) wmma::fill_fragment(sacc[j], 0.0f);
#pragma unroll
        for (int kk = 0; kk < 96; kk += 16) {
            wmma::fragment<wmma::matrix_a, 16, 16, 16, __half, wmma::row_major> af;
            wmma::load_matrix_sync(af, &sm.Qs[warp * 16][kk], 104);
#pragma unroll
            for (int j = 0; j < 4; ++j) {
                wmma::fragment<wmma::matrix_b, 16, 16, 16, __half, wmma::col_major> bf;
                wmma::load_matrix_sync(bf, &sm.Ks[buf][j * 16][kk], 104);
                wmma::mma_sync(sacc[j], af, bf, sacc[j]);
            }
        }

        // Register softmax (warp-local rows). Thread rows: r0=lane>>2, r1=r0+8.
        const bool full = (k0 + 63 <= qb + warp * 16);
        float mx0 = -1e30f, mx1 = -1e30f;
#pragma unroll
        for (int j = 0; j < 4; ++j)
#pragma unroll
            for (int e = 0; e < 8; ++e) {
                float v = sacc[j].x[e] * SCALE;
                if (!full) {
                    int rg = qb + warp * 16 + (lane >> 2) + (((e >> 1) & 1) << 3);
                    int cg = k0 + j * 16 + ((lane & 3) << 1) + (e & 1) + (((e >> 2) & 1) << 3);
                    if (cg > rg) v = -1e30f;
                }
                sacc[j].x[e] = v;
                if ((e >> 1) & 1) mx1 = fmaxf(mx1, v); else mx0 = fmaxf(mx0, v);
            }
        mx0 = fmaxf(mx0, __shfl_xor_sync(0xffffffffu, mx0, 1));
        mx0 = fmaxf(mx0, __shfl_xor_sync(0xffffffffu, mx0, 2));
        mx1 = fmaxf(mx1, __shfl_xor_sync(0xffffffffu, mx1, 1));
        mx1 = fmaxf(mx1, __shfl_xor_sync(0xffffffffu, mx1, 2));
        const float mn0 = fmaxf(m0, mx0), mn1 = fmaxf(m1, mx1);
        const float c0 = __expf(m0 - mn0), c1 = __expf(m1 - mn1);

        float rs0 = 0.0f, rs1 = 0.0f;
        const int rb = warp * 16 + (lane >> 2);
        const int cbb = (lane & 3) << 1;
#pragma unroll
        for (int j = 0; j < 4; ++j) {
            float p[8];
#pragma unroll
            for (int e = 0; e < 8; ++e) {
                p[e] = __expf(sacc[j].x[e] - (((e >> 1) & 1) ? mn1 : mn0));
                if ((e >> 1) & 1) rs1 += p[e]; else rs0 += p[e];
            }
            const int cb = j * 16 + cbb;
            *reinterpret_cast<__half2*>(&sm.Ps[rb][cb])         = __floats2half2_rn(p[0], p[1]);
            *reinterpret_cast<__half2*>(&sm.Ps[rb + 8][cb])     = __floats2half2_rn(p[2], p[3]);
            *reinterpret_cast<__half2*>(&sm.Ps[rb][cb + 8])     = __floats2half2_rn(p[4], p[5]);
            *reinterpret_cast<__half2*>(&sm.Ps[rb + 8][cb + 8]) = __floats2half2_rn(p[6], p[7]);
        }
        rs0 += __shfl_xor_sync(0xffffffffu, rs0, 1);
        rs0 += __shfl_xor_sync(0xffffffffu, rs0, 2);
        rs1 += __shfl_xor_sync(0xffffffffu, rs1, 1);
        rs1 += __shfl_xor_sync(0xffffffffu, rs1, 2);
        l0 = l0 * c0 + rs0;  l1 = l1 * c1 + rs1;
        m0 = mn0;            m1 = mn1;

        // Rescale O, then O += P @ V (all same-warp data: syncwarp only)
#pragma unroll
        for (int j = 0; j < 6; ++j)
#pragma unroll
            for (int e = 0; e < 8; ++e)
                oacc[j].x[e] *= ((e >> 1) & 1) ? c1 : c0;
        __syncwarp();
#pragma unroll
        for (int kk = 0; kk < 64; kk += 16) {
            wmma::fragment<wmma::matrix_a, 16, 16, 16, __half, wmma::row_major> af;
            wmma::load_matrix_sync(af, &sm.Ps[warp * 16][kk], 72);
#pragma unroll
            for (int j = 0; j < 6; ++j) {
                wmma::fragment<wmma::matrix_b, 16, 16, 16, __half, wmma::row_major> bf;
                wmma::load_matrix_sync(bf, &sm.Vs[buf][kk][j * 16], 104);
                wmma::mma_sync(oacc[j], af, bf, oacc[j]);
            }
        }
        buf ^= 1;
    }

    // Epilogue: warp-local. Stage each O fragment into this warp's Ps rows
    // (reinterpreted as fp32 16x24), divide by l, write fp16.
    if ((lane & 3) == 0) {
        sm.l_s[warp * 16 + (lane >> 2)]     = l0;
        sm.l_s[warp * 16 + (lane >> 2) + 8] = l1;
    }
    __syncwarp();
    float* stg = reinterpret_cast<float*>(&sm.Ps[warp * 16][0]);
#pragma unroll
    for (int j = 0; j < 6; ++j) {
        wmma::store_matrix_sync(stg, oacc[j], 24, wmma::mem_row_major);
        __syncwarp();
#pragma unroll
        for (int u = 0; u < 8; ++u) {
            int idx = lane * 8 + u;
            int r = idx >> 4, c = idx & 15;
            float val = stg[r * 24 + c] / sm.l_s[warp * 16 + r];
            size_t o = (size_t)(b * S_ + qb + warp * 16 + r) * HD_ +
                       h * D_ + j * 16 + c;
            g_ctxh[o] = __float2half(val);
        }
        __syncwarp();
    }
}

// ---------------------------------------------------------------------------
// Launch
// ---------------------------------------------------------------------------
extern "C" void kernel_launch(void* const* d_in, const int* in_sizes, int n_in,
                              void* d_out, int out_size) {
    (void)in_sizes; (void)n_in; (void)out_size;
    const float* logits = (const float*)d_in[0];
    const float* Wq = (const float*)d_in[1];
    const float* bq = (const float*)d_in[2];
    const float* Wk = (const float*)d_in[3];
    const float* bk = (const float*)d_in[4];
    const float* Wv = (const float*)d_in[5];
    const float* bv = (const float*)d_in[6];
    const float* Wo = (const float*)d_in[7];
    const float* bo = (const float*)d_in[8];
    float* out = (float*)d_out;

    cudaFuncSetAttribute(flash_attn, cudaFuncAttributeMaxDynamicSharedMemorySize,
                         (int)sizeof(FlashSmem));

    cvt_inputs<<<(M_ * E_ + 255) / 256, 256>>>(logits, Wq, Wk, Wv, Wo);

    {   // fused QKV projection: [8192,1152] @ [1152,3456]
        __half* A; cudaGetSymbolAddress((void**)&A, g_logits_h);
        __half* W; cudaGetSymbolAddress((void**)&W, g_Wqkv_h);
        float*  C; cudaGetSymbolAddress((void**)&C, g_qkvf);
        gemm_big<QKV_><<<dim3(QKV_ / 128, M_ / 128), 256>>>(A, W, C, nullptr);
    }

    rope_pack<<<(B_ * S_ * H_ * (D_ / 2) + 255) / 256, 256>>>(bq, bk, bv);

    flash_attn<<<dim3(S_ / 128, BH_), 256, sizeof(FlashSmem)>>>();

    {   // output projection + bias: [8192,1152] @ [1152,1152] -> out
        __half* A; cudaGetSymbolAddress((void**)&A, g_ctxh);
        __half* W; cudaGetSymbolAddress((void**)&W, g_Wo_h);
        gemm_big<E_><<<dim3(E_ / 128, M_ / 128), 256>>>(A, W, out, bo);
    }
}

// round 8
// speedup vs baseline: 2.8140x; 2.1460x over previous
#include <cuda_runtime.h>
#include <cuda_fp16.h>
#include <mma.h>
#include <math.h>

using namespace nvcuda;

// Problem constants
constexpr int B_  = 4;
constexpr int S_  = 2048;
constexpr int E_  = 1152;
constexpr int H_  = 12;
constexpr int D_  = 96;
constexpr int HD_ = H_ * D_;     // 1152
constexpr int QKV_ = 3 * HD_;    // 3456
constexpr int M_  = B_ * S_;     // 8192
constexpr int BH_ = B_ * H_;     // 48
constexpr int JD_ = D_ / 2;      // 48

// ---------------------------------------------------------------------------
// Scratch (device globals: the allocation-free path)
// ---------------------------------------------------------------------------
__device__ __half g_logits_h[(size_t)M_ * E_];
__device__ __half g_Wqkv_h[(size_t)E_ * QKV_];
__device__ __half g_Wo_h[(size_t)HD_ * E_];
__device__ float  g_qkvf[(size_t)M_ * QKV_];
__device__ __half g_qh[(size_t)M_ * HD_];
__device__ __half g_kh[(size_t)M_ * HD_];
__device__ __half g_vh[(size_t)M_ * HD_];
__device__ __half g_ctxh[(size_t)M_ * HD_];
__device__ float  g_cos[(size_t)S_ * JD_];
__device__ float  g_sin[(size_t)S_ * JD_];

// ---------------------------------------------------------------------------
// cp.async helpers
// ---------------------------------------------------------------------------
__device__ __forceinline__ unsigned smem_u32(const void* p) {
    return (unsigned)__cvta_generic_to_shared(p);
}
__device__ __forceinline__ void cp16(unsigned s, const void* g) {
    asm volatile("cp.async.cg.shared.global [%0], [%1], 16;\n" :: "r"(s), "l"(g));
}
__device__ __forceinline__ void cp_commit() {
    asm volatile("cp.async.commit_group;\n");
}
__device__ __forceinline__ void cp_wait0() {
    asm volatile("cp.async.wait_group 0;\n");
}

// ---------------------------------------------------------------------------
// Elementwise converts
// ---------------------------------------------------------------------------
__global__ void cvt_inputs(const float* __restrict__ logits,
                           const float* __restrict__ Wq,
                           const float* __restrict__ Wk,
                           const float* __restrict__ Wv,
                           const float* __restrict__ Wo) {
    int i = blockIdx.x * blockDim.x + threadIdx.x;
    if (i < M_ * E_) g_logits_h[i] = __float2half(logits[i]);
    if (i < E_ * HD_) {
        int r = i / HD_, c = i % HD_;
        size_t o = (size_t)r * QKV_ + c;
        g_Wqkv_h[o]           = __float2half(Wq[i]);
        g_Wqkv_h[o + HD_]     = __float2half(Wk[i]);
        g_Wqkv_h[o + 2 * HD_] = __float2half(Wv[i]);
        g_Wo_h[i] = __float2half(Wo[i]);
    }
}

// ---------------------------------------------------------------------------
// RoPE angle table over unique (s, j): 98K double sincos instead of 4.7M.
// Math identical to the old per-thread path (theta double, angle fp32,
// sincos double) -> bit-identical cos/sin values.
// ---------------------------------------------------------------------------
__global__ void rope_table() {
    int i = blockIdx.x * blockDim.x + threadIdx.x;
    if (i >= S_ * JD_) return;
    int j = i % JD_, s = i / JD_;
    double theta = exp(-(2.0 * (double)j / (double)D_) * log(10000.0));
    float angf = (float)s * (float)theta;
    double sn, cs;
    sincos((double)angf, &sn, &cs);
    g_cos[i] = (float)cs;
    g_sin[i] = (float)sn;
}

// ---------------------------------------------------------------------------
// Big GEMM: C[M,N] = A[M,1152] @ B[1152,N] (+ bias), fp16 in, fp32 out.
// Block tile 128x128, BK=32, double-buffered cp.async, 8 warps (4x2).
// ---------------------------------------------------------------------------
template<int N>
__global__ __launch_bounds__(256, 2) void gemm_big(const __half* __restrict__ A,
                                                   const __half* __restrict__ Bw,
                                                   float* __restrict__ C,
                                                   const float* __restrict__ bias) {
    __shared__ __half As[2][128][40];
    __shared__ __half Bs[2][32][136];
    const int bm = blockIdx.y * 128;
    const int bn = blockIdx.x * 128;
    const int tid = threadIdx.x;
    const int warp = tid >> 5, wr = warp >> 1, wc = warp & 1;
    const int lane = tid & 31;

    const int ar0 = tid >> 2, ac = (tid & 3) * 8;
    const int br0 = tid >> 4, bc = (tid & 15) * 8;

    wmma::fragment<wmma::accumulator, 16, 16, 16, float> acc[2][4];
#pragma unroll
    for (int i = 0; i < 2; ++i)
#pragma unroll
        for (int j = 0; j < 4; ++j) wmma::fill_fragment(acc[i][j], 0.0f);

    {
        cp16(smem_u32(&As[0][ar0][ac]),      &A[(size_t)(bm + ar0) * 1152 + ac]);
        cp16(smem_u32(&As[0][ar0 + 64][ac]), &A[(size_t)(bm + ar0 + 64) * 1152 + ac]);
        cp16(smem_u32(&Bs[0][br0][bc]),      &Bw[(size_t)br0 * N + bn + bc]);
        cp16(smem_u32(&Bs[0][br0 + 16][bc]), &Bw[(size_t)(br0 + 16) * N + bn + bc]);
        cp_commit();
    }

    int buf = 0;
    constexpr int NIT = 1152 / 32;
    for (int it = 0; it < NIT; ++it) {
        cp_wait0();
        __syncthreads();
        if (it + 1 < NIT) {
            const int k0 = (it + 1) * 32;
            const int nb = buf ^ 1;
            cp16(smem_u32(&As[nb][ar0][ac]),      &A[(size_t)(bm + ar0) * 1152 + k0 + ac]);
            cp16(smem_u32(&As[nb][ar0 + 64][ac]), &A[(size_t)(bm + ar0 + 64) * 1152 + k0 + ac]);
            cp16(smem_u32(&Bs[nb][br0][bc]),      &Bw[(size_t)(k0 + br0) * N + bn + bc]);
            cp16(smem_u32(&Bs[nb][br0 + 16][bc]), &Bw[(size_t)(k0 + br0 + 16) * N + bn + bc]);
            cp_commit();
        }
#pragma unroll
        for (int kk = 0; kk < 32; kk += 16) {
            wmma::fragment<wmma::matrix_a, 16, 16, 16, __half, wmma::row_major> a0, a1;
            wmma::load_matrix_sync(a0, &As[buf][wr * 32][kk], 40);
            wmma::load_matrix_sync(a1, &As[buf][wr * 32 + 16][kk], 40);
#pragma unroll
            for (int j = 0; j < 4; ++j) {
                wmma::fragment<wmma::matrix_b, 16, 16, 16, __half, wmma::row_major> bf;
                wmma::load_matrix_sync(bf, &Bs[buf][kk][wc * 64 + j * 16], 136);
                wmma::mma_sync(acc[0][j], a0, bf, acc[0][j]);
                wmma::mma_sync(acc[1][j], a1, bf, acc[1][j]);
            }
        }
        buf ^= 1;
    }

#pragma unroll
    for (int i = 0; i < 2; ++i)
#pragma unroll
        for (int j = 0; j < 4; ++j) {
            if (bias) {
#pragma unroll
                for (int e = 0; e < 8; ++e) {
                    int c = (lane & 3) * 2 + (e & 1) + ((e >> 2) & 1) * 8;
                    acc[i][j].x[e] += bias[bn + wc * 64 + j * 16 + c];
                }
            }
            wmma::store_matrix_sync(
                &C[(size_t)(bm + wr * 32 + i * 16) * N + bn + wc * 64 + j * 16],
                acc[i][j], N, wmma::mem_row_major);
        }
}

// ---------------------------------------------------------------------------
// RoPE + bias + fp16 pack for q,k; bias + fp16 pack for v. Reads fused qkv
// and the precomputed cos/sin table (no transcendentals here).
// ---------------------------------------------------------------------------
__global__ void rope_pack(const float* __restrict__ bq,
                          const float* __restrict__ bk,
                          const float* __restrict__ bv) {
    const int NP = B_ * S_ * H_ * JD_;
    int gid = blockIdx.x * blockDim.x + threadIdx.x;
    if (gid >= NP) return;
    int j = gid % JD_;
    int t = gid / JD_;
    int h = t % H_; t /= H_;
    int s = t % S_;
    int b = t / S_;

    const size_t row = (size_t)(b * S_ + s);
    const int col = h * D_ + 2 * j;
    const size_t src = row * QKV_ + col;
    const size_t dst = row * HD_ + col;

    const float c   = g_cos[s * JD_ + j];
    const float snf = g_sin[s * JD_ + j];

    float q0 = g_qkvf[src]     + bq[col];
    float q1 = g_qkvf[src + 1] + bq[col + 1];
    g_qh[dst]     = __float2half(q0 * c - q1 * snf);
    g_qh[dst + 1] = __float2half(q1 * c + q0 * snf);

    float k0 = g_qkvf[src + HD_]     + bk[col];
    float k1 = g_qkvf[src + HD_ + 1] + bk[col + 1];
    g_kh[dst]     = __float2half(k0 * c - k1 * snf);
    g_kh[dst + 1] = __float2half(k1 * c + k0 * snf);

    g_vh[dst]     = __float2half(g_qkvf[src + 2 * HD_]     + bv[col]);
    g_vh[dst + 1] = __float2half(g_qkvf[src + 2 * HD_ + 1] + bv[col + 1]);
}

// ---------------------------------------------------------------------------
// Fused flash attention v2 (causal, online softmax, warp-local rows).
// CTA: 128 q-rows of one (b,h); 8 warps, warp w owns rows w*16..w*16+15.
// Per warp: S = 16x64 (4 frags), O = 16x96 (6 frags). Softmax fully in
// registers. K/V double-buffered via cp.async; ONE __syncthreads per k-tile.
// ---------------------------------------------------------------------------
struct FlashSmem {
    __half Qs[128][104];
    __half Ks[2][64][104];
    __half Vs[2][64][104];
    __half Ps[128][72];
    float  l_s[128];
};

__global__ __launch_bounds__(256, 2) void flash_attn() {
    extern __shared__ char smraw[];
    FlashSmem& sm = *reinterpret_cast<FlashSmem*>(smraw);
    const int qi = gridDim.x - 1 - blockIdx.x;      // heavy tiles first
    const int qb = qi * 128;
    const int bh = blockIdx.y, b = bh / H_, h = bh % H_;
    const __half* Q = g_qh + (size_t)b * S_ * HD_ + h * D_;
    const __half* K = g_kh + (size_t)b * S_ * HD_ + h * D_;
    const __half* V = g_vh + (size_t)b * S_ * HD_ + h * D_;
    const int tid = threadIdx.x, lane = tid & 31, warp = tid >> 5;
    const float SCALE = 0.10206207261596577f;       // 1/sqrt(96)

    // Prologue: Q tile (128x96) + K/V tile 0 via cp.async
#pragma unroll
    for (int u = 0; u < 6; ++u) {
        int i = tid + 256 * u;                      // 0..1535
        int r = i / 12, c = (i % 12) * 8;
        cp16(smem_u32(&sm.Qs[r][c]), &Q[(size_t)(qb + r) * HD_ + c]);
    }
#pragma unroll
    for (int u = 0; u < 3; ++u) {
        int i = tid + 256 * u;                      // 0..767
        int r = i / 12, c = (i % 12) * 8;
        cp16(smem_u32(&sm.Ks[0][r][c]), &K[(size_t)r * HD_ + c]);
        cp16(smem_u32(&sm.Vs[0][r][c]), &V[(size_t)r * HD_ + c]);
    }
    cp_commit();

    float m0 = -1e30f, m1 = -1e30f, l0 = 0.0f, l1 = 0.0f;
    wmma::fragment<wmma::accumulator, 16, 16, 16, float> oacc[6];
#pragma unroll
    for (int j = 0; j < 6; ++j) wmma::fill_fragment(oacc[j], 0.0f);

    const int ktiles = (qb + 128) / 64;
    int buf = 0;
    for (int t = 0; t < ktiles; ++t) {
        const int k0 = t * 64;
        cp_wait0();
        __syncthreads();                            // K/V[buf] ready; prev tile done
        if (t + 1 < ktiles) {
            const int kn = k0 + 64, nb = buf ^ 1;
#pragma unroll
            for (int u = 0; u < 3; ++u) {
                int i = tid + 256 * u;
                int r = i / 12, c = (i % 12) * 8;
                cp16(smem_u32(&sm.Ks[nb][r][c]), &K[(size_t)(kn + r) * HD_ + c]);
                cp16(smem_u32(&sm.Vs[nb][r][c]), &V[(size_t)(kn + r) * HD_ + c]);
            }
            cp_commit();
        }

        // S = Q @ K^T : warp rows warp*16, cols 0..64
        wmma::fragment<wmma::accumulator, 16, 16, 16, float> sacc[4];
#pragma unroll
        for (int j = 0; j < 4; ++j) wmma::fill_fragment(sacc[j], 0.0f);
#pragma unroll
        for (int kk = 0; kk < 96; kk += 16) {
            wmma::fragment<wmma::matrix_a, 16, 16, 16, __half, wmma::row_major> af;
            wmma::load_matrix_sync(af, &sm.Qs[warp * 16][kk], 104);
#pragma unroll
            for (int j = 0; j < 4; ++j) {
                wmma::fragment<wmma::matrix_b, 16, 16, 16, __half, wmma::col_major> bf;
                wmma::load_matrix_sync(bf, &sm.Ks[buf][j * 16][kk], 104);
                wmma::mma_sync(sacc[j], af, bf, sacc[j]);
            }
        }

        // Register softmax (warp-local rows). Thread rows: r0=lane>>2, r1=r0+8.
        const bool full = (k0 + 63 <= qb + warp * 16);
        float mx0 = -1e30f, mx1 = -1e30f;
#pragma unroll
        for (int j = 0; j < 4; ++j)
#pragma unroll
            for (int e = 0; e < 8; ++e) {
                float v = sacc[j].x[e] * SCALE;
                if (!full) {
                    int rg = qb + warp * 16 + (lane >> 2) + (((e >> 1) & 1) << 3);
                    int cg = k0 + j * 16 + ((lane & 3) << 1) + (e & 1) + (((e >> 2) & 1) << 3);
                    if (cg > rg) v = -1e30f;
                }
                sacc[j].x[e] = v;
                if ((e >> 1) & 1) mx1 = fmaxf(mx1, v); else mx0 = fmaxf(mx0, v);
            }
        mx0 = fmaxf(mx0, __shfl_xor_sync(0xffffffffu, mx0, 1));
        mx0 = fmaxf(mx0, __shfl_xor_sync(0xffffffffu, mx0, 2));
        mx1 = fmaxf(mx1, __shfl_xor_sync(0xffffffffu, mx1, 1));
        mx1 = fmaxf(mx1, __shfl_xor_sync(0xffffffffu, mx1, 2));
        const float mn0 = fmaxf(m0, mx0), mn1 = fmaxf(m1, mx1);
        const float c0 = __expf(m0 - mn0), c1 = __expf(m1 - mn1);

        float rs0 = 0.0f, rs1 = 0.0f;
        const int rb = warp * 16 + (lane >> 2);
        const int cbb = (lane & 3) << 1;
#pragma unroll
        for (int j = 0; j < 4; ++j) {
            float p[8];
#pragma unroll
            for (int e = 0; e < 8; ++e) {
                p[e] = __expf(sacc[j].x[e] - (((e >> 1) & 1) ? mn1 : mn0));
                if ((e >> 1) & 1) rs1 += p[e]; else rs0 += p[e];
            }
            const int cb = j * 16 + cbb;
            *reinterpret_cast<__half2*>(&sm.Ps[rb][cb])         = __floats2half2_rn(p[0], p[1]);
            *reinterpret_cast<__half2*>(&sm.Ps[rb + 8][cb])     = __floats2half2_rn(p[2], p[3]);
            *reinterpret_cast<__half2*>(&sm.Ps[rb][cb + 8])     = __floats2half2_rn(p[4], p[5]);
            *reinterpret_cast<__half2*>(&sm.Ps[rb + 8][cb + 8]) = __floats2half2_rn(p[6], p[7]);
        }
        rs0 += __shfl_xor_sync(0xffffffffu, rs0, 1);
        rs0 += __shfl_xor_sync(0xffffffffu, rs0, 2);
        rs1 += __shfl_xor_sync(0xffffffffu, rs1, 1);
        rs1 += __shfl_xor_sync(0xffffffffu, rs1, 2);
        l0 = l0 * c0 + rs0;  l1 = l1 * c1 + rs1;
        m0 = mn0;            m1 = mn1;

        // Rescale O, then O += P @ V (all same-warp data: syncwarp only)
#pragma unroll
        for (int j = 0; j < 6; ++j)
#pragma unroll
            for (int e = 0; e < 8; ++e)
                oacc[j].x[e] *= ((e >> 1) & 1) ? c1 : c0;
        __syncwarp();
#pragma unroll
        for (int kk = 0; kk < 64; kk += 16) {
            wmma::fragment<wmma::matrix_a, 16, 16, 16, __half, wmma::row_major> af;
            wmma::load_matrix_sync(af, &sm.Ps[warp * 16][kk], 72);
#pragma unroll
            for (int j = 0; j < 6; ++j) {
                wmma::fragment<wmma::matrix_b, 16, 16, 16, __half, wmma::row_major> bf;
                wmma::load_matrix_sync(bf, &sm.Vs[buf][kk][j * 16], 104);
                wmma::mma_sync(oacc[j], af, bf, oacc[j]);
            }
        }
        buf ^= 1;
    }

    // Epilogue: warp-local. Stage each O fragment into this warp's Ps rows
    // (reinterpreted as fp32 16x24), divide by l, write fp16.
    if ((lane & 3) == 0) {
        sm.l_s[warp * 16 + (lane >> 2)]     = l0;
        sm.l_s[warp * 16 + (lane >> 2) + 8] = l1;
    }
    __syncwarp();
    float* stg = reinterpret_cast<float*>(&sm.Ps[warp * 16][0]);
#pragma unroll
    for (int j = 0; j < 6; ++j) {
        wmma::store_matrix_sync(stg, oacc[j], 24, wmma::mem_row_major);
        __syncwarp();
#pragma unroll
        for (int u = 0; u < 8; ++u) {
            int idx = lane * 8 + u;
            int r = idx >> 4, c = idx & 15;
            float val = stg[r * 24 + c] / sm.l_s[warp * 16 + r];
            size_t o = (size_t)(b * S_ + qb + warp * 16 + r) * HD_ +
                       h * D_ + j * 16 + c;
            g_ctxh[o] = __float2half(val);
        }
        __syncwarp();
    }
}

// ---------------------------------------------------------------------------
// Launch
// ---------------------------------------------------------------------------
extern "C" void kernel_launch(void* const* d_in, const int* in_sizes, int n_in,
                              void* d_out, int out_size) {
    (void)in_sizes; (void)n_in; (void)out_size;
    const float* logits = (const float*)d_in[0];
    const float* Wq = (const float*)d_in[1];
    const float* bq = (const float*)d_in[2];
    const float* Wk = (const float*)d_in[3];
    const float* bk = (const float*)d_in[4];
    const float* Wv = (const float*)d_in[5];
    const float* bv = (const float*)d_in[6];
    const float* Wo = (const float*)d_in[7];
    const float* bo = (const float*)d_in[8];
    float* out = (float*)d_out;

    cudaFuncSetAttribute(flash_attn, cudaFuncAttributeMaxDynamicSharedMemorySize,
                         (int)sizeof(FlashSmem));

    rope_table<<<(S_ * JD_ + 255) / 256, 256>>>();
    cvt_inputs<<<(M_ * E_ + 255) / 256, 256>>>(logits, Wq, Wk, Wv, Wo);

    {   // fused QKV projection: [8192,1152] @ [1152,3456]
        __half* A; cudaGetSymbolAddress((void**)&A, g_logits_h);
        __half* W; cudaGetSymbolAddress((void**)&W, g_Wqkv_h);
        float*  C; cudaGetSymbolAddress((void**)&C, g_qkvf);
        gemm_big<QKV_><<<dim3(QKV_ / 128, M_ / 128), 256>>>(A, W, C, nullptr);
    }

    rope_pack<<<(B_ * S_ * H_ * JD_ + 255) / 256, 256>>>(bq, bk, bv);

    flash_attn<<<dim3(S_ / 128, BH_), 256, sizeof(FlashSmem)>>>();

    {   // output projection + bias: [8192,1152] @ [1152,1152] -> out
        __half* A; cudaGetSymbolAddress((void**)&A, g_ctxh);
        __half* W; cudaGetSymbolAddress((void**)&W, g_Wo_h);
        gemm_big<E_><<<dim3(E_ / 128, M_ / 128), 256>>>(A, W, out, bo);
    }
}

// round 9
// speedup vs baseline: 2.9416x; 1.0454x over previous
#include <cuda_runtime.h>
#include <cuda_fp16.h>
#include <mma.h>
#include <math.h>

using namespace nvcuda;

// Problem constants
constexpr int B_  = 4;
constexpr int S_  = 2048;
constexpr int E_  = 1152;
constexpr int H_  = 12;
constexpr int D_  = 96;
constexpr int HD_ = H_ * D_;     // 1152
constexpr int QKV_ = 3 * HD_;    // 3456
constexpr int M_  = B_ * S_;     // 8192
constexpr int BH_ = B_ * H_;     // 48
constexpr int JD_ = D_ / 2;      // 48

// ---------------------------------------------------------------------------
// Scratch (device globals: the allocation-free path)
// ---------------------------------------------------------------------------
__device__ __half g_logits_h[(size_t)M_ * E_];
__device__ __half g_Wqkv_h[(size_t)E_ * QKV_];
__device__ __half g_Wo_h[(size_t)HD_ * E_];
__device__ __half g_qh[(size_t)M_ * HD_];
__device__ __half g_kh[(size_t)M_ * HD_];
__device__ __half g_vh[(size_t)M_ * HD_];
__device__ __half g_ctxh[(size_t)M_ * HD_];
__device__ float  g_cos[(size_t)S_ * JD_];
__device__ float  g_sin[(size_t)S_ * JD_];

// ---------------------------------------------------------------------------
// cp.async helpers
// ---------------------------------------------------------------------------
__device__ __forceinline__ unsigned smem_u32(const void* p) {
    return (unsigned)__cvta_generic_to_shared(p);
}
__device__ __forceinline__ void cp16(unsigned s, const void* g) {
    asm volatile("cp.async.cg.shared.global [%0], [%1], 16;\n" :: "r"(s), "l"(g));
}
__device__ __forceinline__ void cp_commit() {
    asm volatile("cp.async.commit_group;\n");
}
__device__ __forceinline__ void cp_wait0() {
    asm volatile("cp.async.wait_group 0;\n");
}

// ---------------------------------------------------------------------------
// Elementwise converts
// ---------------------------------------------------------------------------
__global__ void cvt_inputs(const float* __restrict__ logits,
                           const float* __restrict__ Wq,
                           const float* __restrict__ Wk,
                           const float* __restrict__ Wv,
                           const float* __restrict__ Wo) {
    int i = blockIdx.x * blockDim.x + threadIdx.x;
    if (i < M_ * E_) g_logits_h[i] = __float2half(logits[i]);
    if (i < E_ * HD_) {
        int r = i / HD_, c = i % HD_;
        size_t o = (size_t)r * QKV_ + c;
        g_Wqkv_h[o]           = __float2half(Wq[i]);
        g_Wqkv_h[o + HD_]     = __float2half(Wk[i]);
        g_Wqkv_h[o + 2 * HD_] = __float2half(Wv[i]);
        g_Wo_h[i] = __float2half(Wo[i]);
    }
}

// ---------------------------------------------------------------------------
// RoPE angle table over unique (s, j). Same math as before: bit-identical.
// ---------------------------------------------------------------------------
__global__ void rope_table() {
    int i = blockIdx.x * blockDim.x + threadIdx.x;
    if (i >= S_ * JD_) return;
    int j = i % JD_, s = i / JD_;
    double theta = exp(-(2.0 * (double)j / (double)D_) * log(10000.0));
    float angf = (float)s * (float)theta;
    double sn, cs;
    sincos((double)angf, &sn, &cs);
    g_cos[i] = (float)cs;
    g_sin[i] = (float)sn;
}

// ---------------------------------------------------------------------------
// QKV GEMM with fused bias + RoPE + fp16 epilogue.
// C-tile logic identical to gemm_big (128x128, BK=32, double-buffered
// cp.async). Epilogue: accumulator pairs (x[e], x[e+1]) for even e hold
// adjacent cols (c, c+1), c even == a full RoPE pair -> rotate in registers,
// write __half2 directly to g_qh/g_kh/g_vh. N-tile (128) never straddles a
// q/k/v section (1152 = 9*128).
// ---------------------------------------------------------------------------
__global__ __launch_bounds__(256, 2) void gemm_qkv_rope(
        const float* __restrict__ bq, const float* __restrict__ bk,
        const float* __restrict__ bv) {
    const __half* A  = g_logits_h;
    const __half* Bw = g_Wqkv_h;
    constexpr int N = QKV_;
    __shared__ __half As[2][128][40];
    __shared__ __half Bs[2][32][136];
    const int bm = blockIdx.y * 128;
    const int bn = blockIdx.x * 128;
    const int tid = threadIdx.x;
    const int warp = tid >> 5, wr = warp >> 1, wc = warp & 1;
    const int lane = tid & 31;

    const int ar0 = tid >> 2, ac = (tid & 3) * 8;
    const int br0 = tid >> 4, bc = (tid & 15) * 8;

    wmma::fragment<wmma::accumulator, 16, 16, 16, float> acc[2][4];
#pragma unroll
    for (int i = 0; i < 2; ++i)
#pragma unroll
        for (int j = 0; j < 4; ++j) wmma::fill_fragment(acc[i][j], 0.0f);

    {
        cp16(smem_u32(&As[0][ar0][ac]),      &A[(size_t)(bm + ar0) * 1152 + ac]);
        cp16(smem_u32(&As[0][ar0 + 64][ac]), &A[(size_t)(bm + ar0 + 64) * 1152 + ac]);
        cp16(smem_u32(&Bs[0][br0][bc]),      &Bw[(size_t)br0 * N + bn + bc]);
        cp16(smem_u32(&Bs[0][br0 + 16][bc]), &Bw[(size_t)(br0 + 16) * N + bn + bc]);
        cp_commit();
    }

    int buf = 0;
    constexpr int NIT = 1152 / 32;
    for (int it = 0; it < NIT; ++it) {
        cp_wait0();
        __syncthreads();
        if (it + 1 < NIT) {
            const int k0 = (it + 1) * 32;
            const int nb = buf ^ 1;
            cp16(smem_u32(&As[nb][ar0][ac]),      &A[(size_t)(bm + ar0) * 1152 + k0 + ac]);
            cp16(smem_u32(&As[nb][ar0 + 64][ac]), &A[(size_t)(bm + ar0 + 64) * 1152 + k0 + ac]);
            cp16(smem_u32(&Bs[nb][br0][bc]),      &Bw[(size_t)(k0 + br0) * N + bn + bc]);
            cp16(smem_u32(&Bs[nb][br0 + 16][bc]), &Bw[(size_t)(k0 + br0 + 16) * N + bn + bc]);
            cp_commit();
        }
#pragma unroll
        for (int kk = 0; kk < 32; kk += 16) {
            wmma::fragment<wmma::matrix_a, 16, 16, 16, __half, wmma::row_major> a0, a1;
            wmma::load_matrix_sync(a0, &As[buf][wr * 32][kk], 40);
            wmma::load_matrix_sync(a1, &As[buf][wr * 32 + 16][kk], 40);
#pragma unroll
            for (int j = 0; j < 4; ++j) {
                wmma::fragment<wmma::matrix_b, 16, 16, 16, __half, wmma::row_major> bf;
                wmma::load_matrix_sync(bf, &Bs[buf][kk][wc * 64 + j * 16], 136);
                wmma::mma_sync(acc[0][j], a0, bf, acc[0][j]);
                wmma::mma_sync(acc[1][j], a1, bf, acc[1][j]);
            }
        }
        buf ^= 1;
    }

    // Fused epilogue
    const int qkv = bn / HD_;                       // 0=q, 1=k, 2=v (uniform)
    const int colbase = bn % HD_;
    const float* bias = (qkv == 0) ? bq : (qkv == 1) ? bk : bv;
    __half* dst = (qkv == 0) ? g_qh : (qkv == 1) ? g_kh : g_vh;

#pragma unroll
    for (int i = 0; i < 2; ++i)
#pragma unroll
        for (int j = 0; j < 4; ++j) {
            const int r0 = bm + wr * 32 + i * 16 + (lane >> 2);
            const int c0 = colbase + wc * 64 + j * 16 + (lane & 3) * 2;
#pragma unroll
            for (int half = 0; half < 2; ++half) {
                const int cg = c0 + half * 8;       // even; pair (cg, cg+1)
                const int jj = (cg % D_) >> 1;
                const float b0 = bias[cg], b1 = bias[cg + 1];
#pragma unroll
                for (int rr = 0; rr < 2; ++rr) {
                    const int rg = r0 + rr * 8;     // global row = b*S + s
                    const int e0 = rr * 2 + half * 4;
                    float v0 = acc[i][j].x[e0]     + b0;
                    float v1 = acc[i][j].x[e0 + 1] + b1;
                    __half2 w;
                    if (qkv == 2) {
                        w = __floats2half2_rn(v0, v1);
                    } else {
                        const int s = rg & (S_ - 1);
                        const float cv = g_cos[s * JD_ + jj];
                        const float sv = g_sin[s * JD_ + jj];
                        w = __floats2half2_rn(v0 * cv - v1 * sv,
                                              v1 * cv + v0 * sv);
                    }
                    *reinterpret_cast<__half2*>(&dst[(size_t)rg * HD_ + cg]) = w;
                }
            }
        }
}

// ---------------------------------------------------------------------------
// Output GEMM: C[M,1152] = A[M,1152] @ B[1152,1152] + bias, fp32 out.
// ---------------------------------------------------------------------------
template<int N>
__global__ __launch_bounds__(256, 2) void gemm_big(const __half* __restrict__ A,
                                                   const __half* __restrict__ Bw,
                                                   float* __restrict__ C,
                                                   const float* __restrict__ bias) {
    __shared__ __half As[2][128][40];
    __shared__ __half Bs[2][32][136];
    const int bm = blockIdx.y * 128;
    const int bn = blockIdx.x * 128;
    const int tid = threadIdx.x;
    const int warp = tid >> 5, wr = warp >> 1, wc = warp & 1;
    const int lane = tid & 31;

    const int ar0 = tid >> 2, ac = (tid & 3) * 8;
    const int br0 = tid >> 4, bc = (tid & 15) * 8;

    wmma::fragment<wmma::accumulator, 16, 16, 16, float> acc[2][4];
#pragma unroll
    for (int i = 0; i < 2; ++i)
#pragma unroll
        for (int j = 0; j < 4; ++j) wmma::fill_fragment(acc[i][j], 0.0f);

    {
        cp16(smem_u32(&As[0][ar0][ac]),      &A[(size_t)(bm + ar0) * 1152 + ac]);
        cp16(smem_u32(&As[0][ar0 + 64][ac]), &A[(size_t)(bm + ar0 + 64) * 1152 + ac]);
        cp16(smem_u32(&Bs[0][br0][bc]),      &Bw[(size_t)br0 * N + bn + bc]);
        cp16(smem_u32(&Bs[0][br0 + 16][bc]), &Bw[(size_t)(br0 + 16) * N + bn + bc]);
        cp_commit();
    }

    int buf = 0;
    constexpr int NIT = 1152 / 32;
    for (int it = 0; it < NIT; ++it) {
        cp_wait0();
        __syncthreads();
        if (it + 1 < NIT) {
            const int k0 = (it + 1) * 32;
            const int nb = buf ^ 1;
            cp16(smem_u32(&As[nb][ar0][ac]),      &A[(size_t)(bm + ar0) * 1152 + k0 + ac]);
            cp16(smem_u32(&As[nb][ar0 + 64][ac]), &A[(size_t)(bm + ar0 + 64) * 1152 + k0 + ac]);
            cp16(smem_u32(&Bs[nb][br0][bc]),      &Bw[(size_t)(k0 + br0) * N + bn + bc]);
            cp16(smem_u32(&Bs[nb][br0 + 16][bc]), &Bw[(size_t)(k0 + br0 + 16) * N + bn + bc]);
            cp_commit();
        }
#pragma unroll
        for (int kk = 0; kk < 32; kk += 16) {
            wmma::fragment<wmma::matrix_a, 16, 16, 16, __half, wmma::row_major> a0, a1;
            wmma::load_matrix_sync(a0, &As[buf][wr * 32][kk], 40);
            wmma::load_matrix_sync(a1, &As[buf][wr * 32 + 16][kk], 40);
#pragma unroll
            for (int j = 0; j < 4; ++j) {
                wmma::fragment<wmma::matrix_b, 16, 16, 16, __half, wmma::row_major> bf;
                wmma::load_matrix_sync(bf, &Bs[buf][kk][wc * 64 + j * 16], 136);
                wmma::mma_sync(acc[0][j], a0, bf, acc[0][j]);
                wmma::mma_sync(acc[1][j], a1, bf, acc[1][j]);
            }
        }
        buf ^= 1;
    }

#pragma unroll
    for (int i = 0; i < 2; ++i)
#pragma unroll
        for (int j = 0; j < 4; ++j) {
            if (bias) {
#pragma unroll
                for (int e = 0; e < 8; ++e) {
                    int c = (lane & 3) * 2 + (e & 1) + ((e >> 2) & 1) * 8;
                    acc[i][j].x[e] += bias[bn + wc * 64 + j * 16 + c];
                }
            }
            wmma::store_matrix_sync(
                &C[(size_t)(bm + wr * 32 + i * 16) * N + bn + wc * 64 + j * 16],
                acc[i][j], N, wmma::mem_row_major);
        }
}

// ---------------------------------------------------------------------------
// Fused flash attention v2 (causal, online softmax, warp-local rows).
// ---------------------------------------------------------------------------
struct FlashSmem {
    __half Qs[128][104];
    __half Ks[2][64][104];
    __half Vs[2][64][104];
    __half Ps[128][72];
    float  l_s[128];
};

__global__ __launch_bounds__(256, 2) void flash_attn() {
    extern __shared__ char smraw[];
    FlashSmem& sm = *reinterpret_cast<FlashSmem*>(smraw);
    const int qi = gridDim.x - 1 - blockIdx.x;      // heavy tiles first
    const int qb = qi * 128;
    const int bh = blockIdx.y, b = bh / H_, h = bh % H_;
    const __half* Q = g_qh + (size_t)b * S_ * HD_ + h * D_;
    const __half* K = g_kh + (size_t)b * S_ * HD_ + h * D_;
    const __half* V = g_vh + (size_t)b * S_ * HD_ + h * D_;
    const int tid = threadIdx.x, lane = tid & 31, warp = tid >> 5;
    const float SCALE = 0.10206207261596577f;       // 1/sqrt(96)

#pragma unroll
    for (int u = 0; u < 6; ++u) {
        int i = tid + 256 * u;
        int r = i / 12, c = (i % 12) * 8;
        cp16(smem_u32(&sm.Qs[r][c]), &Q[(size_t)(qb + r) * HD_ + c]);
    }
#pragma unroll
    for (int u = 0; u < 3; ++u) {
        int i = tid + 256 * u;
        int r = i / 12, c = (i % 12) * 8;
        cp16(smem_u32(&sm.Ks[0][r][c]), &K[(size_t)r * HD_ + c]);
        cp16(smem_u32(&sm.Vs[0][r][c]), &V[(size_t)r * HD_ + c]);
    }
    cp_commit();

    float m0 = -1e30f, m1 = -1e30f, l0 = 0.0f, l1 = 0.0f;
    wmma::fragment<wmma::accumulator, 16, 16, 16, float> oacc[6];
#pragma unroll
    for (int j = 0; j < 6; ++j) wmma::fill_fragment(oacc[j], 0.0f);

    const int ktiles = (qb + 128) / 64;
    int buf = 0;
    for (int t = 0; t < ktiles; ++t) {
        const int k0 = t * 64;
        cp_wait0();
        __syncthreads();
        if (t + 1 < ktiles) {
            const int kn = k0 + 64, nb = buf ^ 1;
#pragma unroll
            for (int u = 0; u < 3; ++u) {
                int i = tid + 256 * u;
                int r = i / 12, c = (i % 12) * 8;
                cp16(smem_u32(&sm.Ks[nb][r][c]), &K[(size_t)(kn + r) * HD_ + c]);
                cp16(smem_u32(&sm.Vs[nb][r][c]), &V[(size_t)(kn + r) * HD_ + c]);
            }
            cp_commit();
        }

        wmma::fragment<wmma::accumulator, 16, 16, 16, float> sacc[4];
#pragma unroll
        for (int j = 0; j < 4; ++j) wmma::fill_fragment(sacc[j], 0.0f);
#pragma unroll
        for (int kk = 0; kk < 96; kk += 16) {
            wmma::fragment<wmma::matrix_a, 16, 16, 16, __half, wmma::row_major> af;
            wmma::load_matrix_sync(af, &sm.Qs[warp * 16][kk], 104);
#pragma unroll
            for (int j = 0; j < 4; ++j) {
                wmma::fragment<wmma::matrix_b, 16, 16, 16, __half, wmma::col_major> bf;
                wmma::load_matrix_sync(bf, &sm.Ks[buf][j * 16][kk], 104);
                wmma::mma_sync(sacc[j], af, bf, sacc[j]);
            }
        }

        const bool full = (k0 + 63 <= qb + warp * 16);
        float mx0 = -1e30f, mx1 = -1e30f;
#pragma unroll
        for (int j = 0; j < 4; ++j)
#pragma unroll
            for (int e = 0; e < 8; ++e) {
                float v = sacc[j].x[e] * SCALE;
                if (!full) {
                    int rg = qb + warp * 16 + (lane >> 2) + (((e >> 1) & 1) << 3);
                    int cg = k0 + j * 16 + ((lane & 3) << 1) + (e & 1) + (((e >> 2) & 1) << 3);
                    if (cg > rg) v = -1e30f;
                }
                sacc[j].x[e] = v;
                if ((e >> 1) & 1) mx1 = fmaxf(mx1, v); else mx0 = fmaxf(mx0, v);
            }
        mx0 = fmaxf(mx0, __shfl_xor_sync(0xffffffffu, mx0, 1));
        mx0 = fmaxf(mx0, __shfl_xor_sync(0xffffffffu, mx0, 2));
        mx1 = fmaxf(mx1, __shfl_xor_sync(0xffffffffu, mx1, 1));
        mx1 = fmaxf(mx1, __shfl_xor_sync(0xffffffffu, mx1, 2));
        const float mn0 = fmaxf(m0, mx0), mn1 = fmaxf(m1, mx1);
        const float c0 = __expf(m0 - mn0), c1 = __expf(m1 - mn1);

        float rs0 = 0.0f, rs1 = 0.0f;
        const int rb = warp * 16 + (lane >> 2);
        const int cbb = (lane & 3) << 1;
#pragma unroll
        for (int j = 0; j < 4; ++j) {
            float p[8];
#pragma unroll
            for (int e = 0; e < 8; ++e) {
                p[e] = __expf(sacc[j].x[e] - (((e >> 1) & 1) ? mn1 : mn0));
                if ((e >> 1) & 1) rs1 += p[e]; else rs0 += p[e];
            }
            const int cb = j * 16 + cbb;
            *reinterpret_cast<__half2*>(&sm.Ps[rb][cb])         = __floats2half2_rn(p[0], p[1]);
            *reinterpret_cast<__half2*>(&sm.Ps[rb + 8][cb])     = __floats2half2_rn(p[2], p[3]);
            *reinterpret_cast<__half2*>(&sm.Ps[rb][cb + 8])     = __floats2half2_rn(p[4], p[5]);
            *reinterpret_cast<__half2*>(&sm.Ps[rb + 8][cb + 8]) = __floats2half2_rn(p[6], p[7]);
        }
        rs0 += __shfl_xor_sync(0xffffffffu, rs0, 1);
        rs0 += __shfl_xor_sync(0xffffffffu, rs0, 2);
        rs1 += __shfl_xor_sync(0xffffffffu, rs1, 1);
        rs1 += __shfl_xor_sync(0xffffffffu, rs1, 2);
        l0 = l0 * c0 + rs0;  l1 = l1 * c1 + rs1;
        m0 = mn0;            m1 = mn1;

#pragma unroll
        for (int j = 0; j < 6; ++j)
#pragma unroll
            for (int e = 0; e < 8; ++e)
                oacc[j].x[e] *= ((e >> 1) & 1) ? c1 : c0;
        __syncwarp();
#pragma unroll
        for (int kk = 0; kk < 64; kk += 16) {
            wmma::fragment<wmma::matrix_a, 16, 16, 16, __half, wmma::row_major> af;
            wmma::load_matrix_sync(af, &sm.Ps[warp * 16][kk], 72);
#pragma unroll
            for (int j = 0; j < 6; ++j) {
                wmma::fragment<wmma::matrix_b, 16, 16, 16, __half, wmma::row_major> bf;
                wmma::load_matrix_sync(bf, &sm.Vs[buf][kk][j * 16], 104);
                wmma::mma_sync(oacc[j], af, bf, oacc[j]);
            }
        }
        buf ^= 1;
    }

    if ((lane & 3) == 0) {
        sm.l_s[warp * 16 + (lane >> 2)]     = l0;
        sm.l_s[warp * 16 + (lane >> 2) + 8] = l1;
    }
    __syncwarp();
    float* stg = reinterpret_cast<float*>(&sm.Ps[warp * 16][0]);
#pragma unroll
    for (int j = 0; j < 6; ++j) {
        wmma::store_matrix_sync(stg, oacc[j], 24, wmma::mem_row_major);
        __syncwarp();
#pragma unroll
        for (int u = 0; u < 8; ++u) {
            int idx = lane * 8 + u;
            int r = idx >> 4, c = idx & 15;
            float val = stg[r * 24 + c] / sm.l_s[warp * 16 + r];
            size_t o = (size_t)(b * S_ + qb + warp * 16 + r) * HD_ +
                       h * D_ + j * 16 + c;
            g_ctxh[o] = __float2half(val);
        }
        __syncwarp();
    }
}

// ---------------------------------------------------------------------------
// Launch
// ---------------------------------------------------------------------------
extern "C" void kernel_launch(void* const* d_in, const int* in_sizes, int n_in,
                              void* d_out, int out_size) {
    (void)in_sizes; (void)n_in; (void)out_size;
    const float* logits = (const float*)d_in[0];
    const float* Wq = (const float*)d_in[1];
    const float* bq = (const float*)d_in[2];
    const float* Wk = (const float*)d_in[3];
    const float* bk = (const float*)d_in[4];
    const float* Wv = (const float*)d_in[5];
    const float* bv = (const float*)d_in[6];
    const float* Wo = (const float*)d_in[7];
    const float* bo = (const float*)d_in[8];
    float* out = (float*)d_out;

    cudaFuncSetAttribute(flash_attn, cudaFuncAttributeMaxDynamicSharedMemorySize,
                         (int)sizeof(FlashSmem));

    rope_table<<<(S_ * JD_ + 255) / 256, 256>>>();
    cvt_inputs<<<(M_ * E_ + 255) / 256, 256>>>(logits, Wq, Wk, Wv, Wo);

    // fused QKV projection + bias + RoPE + fp16 pack
    gemm_qkv_rope<<<dim3(QKV_ / 128, M_ / 128), 256>>>(bq, bk, bv);

    flash_attn<<<dim3(S_ / 128, BH_), 256, sizeof(FlashSmem)>>>();

    {   // output projection + bias: [8192,1152] @ [1152,1152] -> out
        __half* A; cudaGetSymbolAddress((void**)&A, g_ctxh);
        __half* W; cudaGetSymbolAddress((void**)&W, g_Wo_h);
        gemm_big<E_><<<dim3(E_ / 128, M_ / 128), 256>>>(A, W, out, bo);
    }
}

// round 11
// speedup vs baseline: 3.3278x; 1.1313x over previous
#include <cuda_runtime.h>
#include <cuda_fp16.h>
#include <mma.h>
#include <math.h>

using namespace nvcuda;

// Problem constants
constexpr int B_  = 4;
constexpr int S_  = 2048;
constexpr int E_  = 1152;
constexpr int H_  = 12;
constexpr int D_  = 96;
constexpr int HD_ = H_ * D_;     // 1152
constexpr int QKV_ = 3 * HD_;    // 3456
constexpr int M_  = B_ * S_;     // 8192
constexpr int BH_ = B_ * H_;     // 48
constexpr int JD_ = D_ / 2;      // 48

// ---------------------------------------------------------------------------
// Scratch (device globals: the allocation-free path)
// ---------------------------------------------------------------------------
__device__ __half g_logits_h[(size_t)M_ * E_];
__device__ __half g_Wqkv_h[(size_t)E_ * QKV_];
__device__ __half g_Wo_h[(size_t)HD_ * E_];
__device__ __half g_qh[(size_t)M_ * HD_];
__device__ __half g_kh[(size_t)M_ * HD_];
__device__ __half g_vh[(size_t)M_ * HD_];
__device__ __half g_ctxh[(size_t)M_ * HD_];
__device__ float  g_cos[(size_t)S_ * JD_];
__device__ float  g_sin[(size_t)S_ * JD_];

// ---------------------------------------------------------------------------
// cp.async / mma helpers
// ---------------------------------------------------------------------------
__device__ __forceinline__ unsigned smem_u32(const void* p) {
    return (unsigned)__cvta_generic_to_shared(p);
}
__device__ __forceinline__ void cp16(unsigned s, const void* g) {
    asm volatile("cp.async.cg.shared.global [%0], [%1], 16;\n" :: "r"(s), "l"(g));
}
__device__ __forceinline__ void cp_commit() {
    asm volatile("cp.async.commit_group;\n");
}
__device__ __forceinline__ void cp_wait0() {
    asm volatile("cp.async.wait_group 0;\n");
}
__device__ __forceinline__ unsigned h2u(float a, float b) {
    __half2 h = __floats2half2_rn(a, b);
    return *reinterpret_cast<unsigned*>(&h);
}
__device__ __forceinline__ void ldsm4t(unsigned& r0, unsigned& r1,
                                       unsigned& r2, unsigned& r3, unsigned addr) {
    asm volatile("ldmatrix.sync.aligned.m8n8.x4.trans.shared.b16 {%0,%1,%2,%3}, [%4];"
                 : "=r"(r0), "=r"(r1), "=r"(r2), "=r"(r3) : "r"(addr));
}
__device__ __forceinline__ void mma16816(float* o, const unsigned* a,
                                         unsigned b0, unsigned b1) {
    asm volatile(
        "mma.sync.aligned.m16n8k16.row.col.f32.f16.f16.f32 "
        "{%0,%1,%2,%3}, {%4,%5,%6,%7}, {%8,%9}, {%0,%1,%2,%3};"
        : "+f"(o[0]), "+f"(o[1]), "+f"(o[2]), "+f"(o[3])
        : "r"(a[0]), "r"(a[1]), "r"(a[2]), "r"(a[3]), "r"(b0), "r"(b1));
}

// ---------------------------------------------------------------------------
// Elementwise converts
// ---------------------------------------------------------------------------
__global__ void cvt_inputs(const float* __restrict__ logits,
                           const float* __restrict__ Wq,
                           const float* __restrict__ Wk,
                           const float* __restrict__ Wv,
                           const float* __restrict__ Wo) {
    int i = blockIdx.x * blockDim.x + threadIdx.x;
    if (i < M_ * E_) g_logits_h[i] = __float2half(logits[i]);
    if (i < E_ * HD_) {
        int r = i / HD_, c = i % HD_;
        size_t o = (size_t)r * QKV_ + c;
        g_Wqkv_h[o]           = __float2half(Wq[i]);
        g_Wqkv_h[o + HD_]     = __float2half(Wk[i]);
        g_Wqkv_h[o + 2 * HD_] = __float2half(Wv[i]);
        g_Wo_h[i] = __float2half(Wo[i]);
    }
}

// ---------------------------------------------------------------------------
// RoPE angle table over unique (s, j). Same math as before: bit-identical.
// ---------------------------------------------------------------------------
__global__ void rope_table() {
    int i = blockIdx.x * blockDim.x + threadIdx.x;
    if (i >= S_ * JD_) return;
    int j = i % JD_, s = i / JD_;
    double theta = exp(-(2.0 * (double)j / (double)D_) * log(10000.0));
    float angf = (float)s * (float)theta;
    double sn, cs;
    sincos((double)angf, &sn, &cs);
    g_cos[i] = (float)cs;
    g_sin[i] = (float)sn;
}

// ---------------------------------------------------------------------------
// QKV GEMM with fused bias + RoPE + fp16 epilogue (unchanged from R9).
// ---------------------------------------------------------------------------
__global__ __launch_bounds__(256, 2) void gemm_qkv_rope(
        const float* __restrict__ bq, const float* __restrict__ bk,
        const float* __restrict__ bv) {
    const __half* A  = g_logits_h;
    const __half* Bw = g_Wqkv_h;
    constexpr int N = QKV_;
    __shared__ __half As[2][128][40];
    __shared__ __half Bs[2][32][136];
    const int bm = blockIdx.y * 128;
    const int bn = blockIdx.x * 128;
    const int tid = threadIdx.x;
    const int warp = tid >> 5, wr = warp >> 1, wc = warp & 1;
    const int lane = tid & 31;

    const int ar0 = tid >> 2, ac = (tid & 3) * 8;
    const int br0 = tid >> 4, bc = (tid & 15) * 8;

    wmma::fragment<wmma::accumulator, 16, 16, 16, float> acc[2][4];
#pragma unroll
    for (int i = 0; i < 2; ++i)
#pragma unroll
        for (int j = 0; j < 4; ++j) wmma::fill_fragment(acc[i][j], 0.0f);

    {
        cp16(smem_u32(&As[0][ar0][ac]),      &A[(size_t)(bm + ar0) * 1152 + ac]);
        cp16(smem_u32(&As[0][ar0 + 64][ac]), &A[(size_t)(bm + ar0 + 64) * 1152 + ac]);
        cp16(smem_u32(&Bs[0][br0][bc]),      &Bw[(size_t)br0 * N + bn + bc]);
        cp16(smem_u32(&Bs[0][br0 + 16][bc]), &Bw[(size_t)(br0 + 16) * N + bn + bc]);
        cp_commit();
    }

    int buf = 0;
    constexpr int NIT = 1152 / 32;
    for (int it = 0; it < NIT; ++it) {
        cp_wait0();
        __syncthreads();
        if (it + 1 < NIT) {
            const int k0 = (it + 1) * 32;
            const int nb = buf ^ 1;
            cp16(smem_u32(&As[nb][ar0][ac]),      &A[(size_t)(bm + ar0) * 1152 + k0 + ac]);
            cp16(smem_u32(&As[nb][ar0 + 64][ac]), &A[(size_t)(bm + ar0 + 64) * 1152 + k0 + ac]);
            cp16(smem_u32(&Bs[nb][br0][bc]),      &Bw[(size_t)(k0 + br0) * N + bn + bc]);
            cp16(smem_u32(&Bs[nb][br0 + 16][bc]), &Bw[(size_t)(k0 + br0 + 16) * N + bn + bc]);
            cp_commit();
        }
#pragma unroll
        for (int kk = 0; kk < 32; kk += 16) {
            wmma::fragment<wmma::matrix_a, 16, 16, 16, __half, wmma::row_major> a0, a1;
            wmma::load_matrix_sync(a0, &As[buf][wr * 32][kk], 40);
            wmma::load_matrix_sync(a1, &As[buf][wr * 32 + 16][kk], 40);
#pragma unroll
            for (int j = 0; j < 4; ++j) {
                wmma::fragment<wmma::matrix_b, 16, 16, 16, __half, wmma::row_major> bf;
                wmma::load_matrix_sync(bf, &Bs[buf][kk][wc * 64 + j * 16], 136);
                wmma::mma_sync(acc[0][j], a0, bf, acc[0][j]);
                wmma::mma_sync(acc[1][j], a1, bf, acc[1][j]);
            }
        }
        buf ^= 1;
    }

    const int qkv = bn / HD_;                       // 0=q, 1=k, 2=v (uniform)
    const int colbase = bn % HD_;
    const float* bias = (qkv == 0) ? bq : (qkv == 1) ? bk : bv;
    __half* dst = (qkv == 0) ? g_qh : (qkv == 1) ? g_kh : g_vh;

#pragma unroll
    for (int i = 0; i < 2; ++i)
#pragma unroll
        for (int j = 0; j < 4; ++j) {
            const int r0 = bm + wr * 32 + i * 16 + (lane >> 2);
            const int c0 = colbase + wc * 64 + j * 16 + (lane & 3) * 2;
#pragma unroll
            for (int half = 0; half < 2; ++half) {
                const int cg = c0 + half * 8;
                const int jj = (cg % D_) >> 1;
                const float b0 = bias[cg], b1 = bias[cg + 1];
#pragma unroll
                for (int rr = 0; rr < 2; ++rr) {
                    const int rg = r0 + rr * 8;
                    const int e0 = rr * 2 + half * 4;
                    float v0 = acc[i][j].x[e0]     + b0;
                    float v1 = acc[i][j].x[e0 + 1] + b1;
                    __half2 w;
                    if (qkv == 2) {
                        w = __floats2half2_rn(v0, v1);
                    } else {
                        const int s = rg & (S_ - 1);
                        const float cv = g_cos[s * JD_ + jj];
                        const float sv = g_sin[s * JD_ + jj];
                        w = __floats2half2_rn(v0 * cv - v1 * sv,
                                              v1 * cv + v0 * sv);
                    }
                    *reinterpret_cast<__half2*>(&dst[(size_t)rg * HD_ + cg]) = w;
                }
            }
        }
}

// ---------------------------------------------------------------------------
// Output GEMM (unchanged from R9).
// ---------------------------------------------------------------------------
template<int N>
__global__ __launch_bounds__(256, 2) void gemm_big(const __half* __restrict__ A,
                                                   const __half* __restrict__ Bw,
                                                   float* __restrict__ C,
                                                   const float* __restrict__ bias) {
    __shared__ __half As[2][128][40];
    __shared__ __half Bs[2][32][136];
    const int bm = blockIdx.y * 128;
    const int bn = blockIdx.x * 128;
    const int tid = threadIdx.x;
    const int warp = tid >> 5, wr = warp >> 1, wc = warp & 1;
    const int lane = tid & 31;

    const int ar0 = tid >> 2, ac = (tid & 3) * 8;
    const int br0 = tid >> 4, bc = (tid & 15) * 8;

    wmma::fragment<wmma::accumulator, 16, 16, 16, float> acc[2][4];
#pragma unroll
    for (int i = 0; i < 2; ++i)
#pragma unroll
        for (int j = 0; j < 4; ++j) wmma::fill_fragment(acc[i][j], 0.0f);

    {
        cp16(smem_u32(&As[0][ar0][ac]),      &A[(size_t)(bm + ar0) * 1152 + ac]);
        cp16(smem_u32(&As[0][ar0 + 64][ac]), &A[(size_t)(bm + ar0 + 64) * 1152 + ac]);
        cp16(smem_u32(&Bs[0][br0][bc]),      &Bw[(size_t)br0 * N + bn + bc]);
        cp16(smem_u32(&Bs[0][br0 + 16][bc]), &Bw[(size_t)(br0 + 16) * N + bn + bc]);
        cp_commit();
    }

    int buf = 0;
    constexpr int NIT = 1152 / 32;
    for (int it = 0; it < NIT; ++it) {
        cp_wait0();
        __syncthreads();
        if (it + 1 < NIT) {
            const int k0 = (it + 1) * 32;
            const int nb = buf ^ 1;
            cp16(smem_u32(&As[nb][ar0][ac]),      &A[(size_t)(bm + ar0) * 1152 + k0 + ac]);
            cp16(smem_u32(&As[nb][ar0 + 64][ac]), &A[(size_t)(bm + ar0 + 64) * 1152 + k0 + ac]);
            cp16(smem_u32(&Bs[nb][br0][bc]),      &Bw[(size_t)(k0 + br0) * N + bn + bc]);
            cp16(smem_u32(&Bs[nb][br0 + 16][bc]), &Bw[(size_t)(k0 + br0 + 16) * N + bn + bc]);
            cp_commit();
        }
#pragma unroll
        for (int kk = 0; kk < 32; kk += 16) {
            wmma::fragment<wmma::matrix_a, 16, 16, 16, __half, wmma::row_major> a0, a1;
            wmma::load_matrix_sync(a0, &As[buf][wr * 32][kk], 40);
            wmma::load_matrix_sync(a1, &As[buf][wr * 32 + 16][kk], 40);
#pragma unroll
            for (int j = 0; j < 4; ++j) {
                wmma::fragment<wmma::matrix_b, 16, 16, 16, __half, wmma::row_major> bf;
                wmma::load_matrix_sync(bf, &Bs[buf][kk][wc * 64 + j * 16], 136);
                wmma::mma_sync(acc[0][j], a0, bf, acc[0][j]);
                wmma::mma_sync(acc[1][j], a1, bf, acc[1][j]);
            }
        }
        buf ^= 1;
    }

#pragma unroll
    for (int i = 0; i < 2; ++i)
#pragma unroll
        for (int j = 0; j < 4; ++j) {
            if (bias) {
#pragma unroll
                for (int e = 0; e < 8; ++e) {
                    int c = (lane & 3) * 2 + (e & 1) + ((e >> 2) & 1) * 8;
                    acc[i][j].x[e] += bias[bn + wc * 64 + j * 16 + c];
                }
            }
            wmma::store_matrix_sync(
                &C[(size_t)(bm + wr * 32 + i * 16) * N + bn + wc * 64 + j * 16],
                acc[i][j], N, wmma::mem_row_major);
        }
}

// ---------------------------------------------------------------------------
// Fused flash attention v3: P never touches smem.
// QK^T via wmma (acc layout: row = lane/4 + 8*((e>>1)&1),
// col = (lane&3)*2 + (e&1) + 8*((e>>2)&1)) -> exp'd probs packed straight
// into mma.m16n8k16 A-operands (identical layout). PV via raw mma with B
// frags ldmatrix.x4.trans'd from Vs. O = 12 raw m16n8 accums; epilogue is
// direct half2 global stores (l0/l1 thread-resident). Softmax in log2
// domain (exp2f). smem 78KB, 2 CTAs/SM.
// ---------------------------------------------------------------------------
struct FlashSmem {
    __half Qs[128][104];
    __half Ks[2][64][104];
    __half Vs[2][64][104];
};

__global__ __launch_bounds__(256, 2) void flash_attn() {
    extern __shared__ char smraw[];
    FlashSmem& sm = *reinterpret_cast<FlashSmem*>(smraw);
    const int qi = gridDim.x - 1 - blockIdx.x;      // heavy tiles first
    const int qb = qi * 128;
    const int bh = blockIdx.y, b = bh / H_, h = bh % H_;
    const __half* Q = g_qh + (size_t)b * S_ * HD_ + h * D_;
    const __half* K = g_kh + (size_t)b * S_ * HD_ + h * D_;
    const __half* V = g_vh + (size_t)b * S_ * HD_ + h * D_;
    const int tid = threadIdx.x, lane = tid & 31, warp = tid >> 5;
    // scale * log2(e): softmax done base-2
    const float C2 = 0.10206207261596577f * 1.4426950408889634f;

#pragma unroll
    for (int u = 0; u < 6; ++u) {
        int i = tid + 256 * u;
        int r = i / 12, c = (i % 12) * 8;
        cp16(smem_u32(&sm.Qs[r][c]), &Q[(size_t)(qb + r) * HD_ + c]);
    }
#pragma unroll
    for (int u = 0; u < 3; ++u) {
        int i = tid + 256 * u;
        int r = i / 12, c = (i % 12) * 8;
        cp16(smem_u32(&sm.Ks[0][r][c]), &K[(size_t)r * HD_ + c]);
        cp16(smem_u32(&sm.Vs[0][r][c]), &V[(size_t)r * HD_ + c]);
    }
    cp_commit();

    float m0 = -1e30f, m1 = -1e30f, l0 = 0.0f, l1 = 0.0f;
    float o[12][4];
#pragma unroll
    for (int m = 0; m < 12; ++m)
#pragma unroll
        for (int e = 0; e < 4; ++e) o[m][e] = 0.0f;

    const int ktiles = (qb + 128) / 64;
    int buf = 0;
    for (int t = 0; t < ktiles; ++t) {
        const int k0 = t * 64;
        cp_wait0();
        __syncthreads();                            // K/V[buf] ready
        if (t + 1 < ktiles) {
            const int kn = k0 + 64, nb = buf ^ 1;
#pragma unroll
            for (int u = 0; u < 3; ++u) {
                int i = tid + 256 * u;
                int r = i / 12, c = (i % 12) * 8;
                cp16(smem_u32(&sm.Ks[nb][r][c]), &K[(size_t)(kn + r) * HD_ + c]);
                cp16(smem_u32(&sm.Vs[nb][r][c]), &V[(size_t)(kn + r) * HD_ + c]);
            }
            cp_commit();
        }

        // S = Q @ K^T (wmma), warp rows warp*16..+15, cols k0..k0+63
        wmma::fragment<wmma::accumulator, 16, 16, 16, float> sacc[4];
#pragma unroll
        for (int j = 0; j < 4; ++j) wmma::fill_fragment(sacc[j], 0.0f);
#pragma unroll
        for (int kk = 0; kk < 96; kk += 16) {
            wmma::fragment<wmma::matrix_a, 16, 16, 16, __half, wmma::row_major> af;
            wmma::load_matrix_sync(af, &sm.Qs[warp * 16][kk], 104);
#pragma unroll
            for (int j = 0; j < 4; ++j) {
                wmma::fragment<wmma::matrix_b, 16, 16, 16, __half, wmma::col_major> bf;
                wmma::load_matrix_sync(bf, &sm.Ks[buf][j * 16][kk], 104);
                wmma::mma_sync(sacc[j], af, bf, sacc[j]);
            }
        }

        // Scale to log2 domain + causal mask + row max (registers only)
        const bool full = (k0 + 63 <= qb + warp * 16);
        float mx0 = -1e30f, mx1 = -1e30f;
#pragma unroll
        for (int j = 0; j < 4; ++j)
#pragma unroll
            for (int e = 0; e < 8; ++e) {
                float v = sacc[j].x[e] * C2;
                if (!full) {
                    int rg = qb + warp * 16 + (lane >> 2) + (((e >> 1) & 1) << 3);
                    int cg = k0 + j * 16 + ((lane & 3) << 1) + (e & 1) + (((e >> 2) & 1) << 3);
                    if (cg > rg) v = -1e30f;
                }
                sacc[j].x[e] = v;
                if ((e >> 1) & 1) mx1 = fmaxf(mx1, v); else mx0 = fmaxf(mx0, v);
            }
        mx0 = fmaxf(mx0, __shfl_xor_sync(0xffffffffu, mx0, 1));
        mx0 = fmaxf(mx0, __shfl_xor_sync(0xffffffffu, mx0, 2));
        mx1 = fmaxf(mx1, __shfl_xor_sync(0xffffffffu, mx1, 1));
        mx1 = fmaxf(mx1, __shfl_xor_sync(0xffffffffu, mx1, 2));
        const float mn0 = fmaxf(m0, mx0), mn1 = fmaxf(m1, mx1);
        const float c0 = exp2f(m0 - mn0), c1 = exp2f(m1 - mn1);

        // exp2 + pack P directly into mma A-operands (same layout as acc)
        unsigned pa[4][4];
        float rs0 = 0.0f, rs1 = 0.0f;
#pragma unroll
        for (int j = 0; j < 4; ++j) {
            float p[8];
#pragma unroll
            for (int e = 0; e < 8; ++e) {
                p[e] = exp2f(sacc[j].x[e] - (((e >> 1) & 1) ? mn1 : mn0));
                if ((e >> 1) & 1) rs1 += p[e]; else rs0 += p[e];
            }
            pa[j][0] = h2u(p[0], p[1]);
            pa[j][1] = h2u(p[2], p[3]);
            pa[j][2] = h2u(p[4], p[5]);
            pa[j][3] = h2u(p[6], p[7]);
        }
        rs0 += __shfl_xor_sync(0xffffffffu, rs0, 1);
        rs0 += __shfl_xor_sync(0xffffffffu, rs0, 2);
        rs1 += __shfl_xor_sync(0xffffffffu, rs1, 1);
        rs1 += __shfl_xor_sync(0xffffffffu, rs1, 2);
        l0 = l0 * c0 + rs0;  l1 = l1 * c1 + rs1;
        m0 = mn0;            m1 = mn1;

        // Rescale O (rows r -> c0, r+8 -> c1), then O += P @ V (raw mma)
#pragma unroll
        for (int m = 0; m < 12; ++m) {
            o[m][0] *= c0; o[m][1] *= c0;
            o[m][2] *= c1; o[m][3] *= c1;
        }
#pragma unroll
        for (int nn = 0; nn < 6; ++nn) {
            const unsigned vaddr = smem_u32(
                &sm.Vs[buf][(lane & 15)][nn * 16 + ((lane >> 4) << 3)]);
#pragma unroll
            for (int j = 0; j < 4; ++j) {
                unsigned b0, b1, b2, b3;
                ldsm4t(b0, b1, b2, b3, vaddr + (unsigned)(j * 16) * 208u);
                mma16816(o[2 * nn],     pa[j], b0, b1);
                mma16816(o[2 * nn + 1], pa[j], b2, b3);
            }
        }
        buf ^= 1;
    }

    // Epilogue: direct half2 stores, l0/l1 already in registers.
    const float inv0 = 1.0f / l0, inv1 = 1.0f / l1;
    const size_t row0 = (size_t)(b * S_ + qb + warp * 16 + (lane >> 2));
    const int colb = h * D_ + (lane & 3) * 2;
#pragma unroll
    for (int m = 0; m < 12; ++m) {
        const int col = colb + m * 8;
        *reinterpret_cast<__half2*>(&g_ctxh[row0 * HD_ + col]) =
            __floats2half2_rn(o[m][0] * inv0, o[m][1] * inv0);
        *reinterpret_cast<__half2*>(&g_ctxh[(row0 + 8) * HD_ + col]) =
            __floats2half2_rn(o[m][2] * inv1, o[m][3] * inv1);
    }
}

// ---------------------------------------------------------------------------
// Launch
// ---------------------------------------------------------------------------
extern "C" void kernel_launch(void* const* d_in, const int* in_sizes, int n_in,
                              void* d_out, int out_size) {
    (void)in_sizes; (void)n_in; (void)out_size;
    const float* logits = (const float*)d_in[0];
    const float* Wq = (const float*)d_in[1];
    const float* bq = (const float*)d_in[2];
    const float* Wk = (const float*)d_in[3];
    const float* bk = (const float*)d_in[4];
    const float* Wv = (const float*)d_in[5];
    const float* bv = (const float*)d_in[6];
    const float* Wo = (const float*)d_in[7];
    const float* bo = (const float*)d_in[8];
    float* out = (float*)d_out;

    cudaFuncSetAttribute(flash_attn, cudaFuncAttributeMaxDynamicSharedMemorySize,
                         (int)sizeof(FlashSmem));

    rope_table<<<(S_ * JD_ + 255) / 256, 256>>>();
    cvt_inputs<<<(M_ * E_ + 255) / 256, 256>>>(logits, Wq, Wk, Wv, Wo);

    // fused QKV projection + bias + RoPE + fp16 pack
    gemm_qkv_rope<<<dim3(QKV_ / 128, M_ / 128), 256>>>(bq, bk, bv);

    flash_attn<<<dim3(S_ / 128, BH_), 256, sizeof(FlashSmem)>>>();

    {   // output projection + bias: [8192,1152] @ [1152,1152] -> out
        __half* A; cudaGetSymbolAddress((void**)&A, g_ctxh);
        __half* W; cudaGetSymbolAddress((void**)&W, g_Wo_h);
        gemm_big<E_><<<dim3(E_ / 128, M_ / 128), 256>>>(A, W, out, bo);
    }
}